// round 4
// baseline (speedup 1.0000x reference)
#include <cuda_runtime.h>
#include <cuda_bf16.h>
#include <cstdint>

// ---------------------------------------------------------------------------
// Problem constants (B=1)
// ---------------------------------------------------------------------------
static constexpr int C_   = 256;
static constexpr int HW_  = 4096;     // 64*64
static constexpr int S_   = 32768;    // 8*64*64
static constexpr int SA_  = 20480;    // 5*64*64 active (last 5 frames)
static constexpr int S0_  = S_ - SA_; // 12288
static constexpr float INV_TEMP = 10.0f;

// ---------------------------------------------------------------------------
// Device scratch
// ---------------------------------------------------------------------------
__device__ __align__(16) __nv_bfloat16 g_keyT_hi[SA_ * C_];   // [j][c]
__device__ __align__(16) __nv_bfloat16 g_keyT_lo[SA_ * C_];
__device__ __align__(16) __nv_bfloat16 g_val_hi [C_ * SA_];   // [a][j]
__device__ __align__(16) __nv_bfloat16 g_val_lo [C_ * SA_];
__device__ __align__(16) __nv_bfloat16 g_KsT_hi [C_ * SA_];   // [o][j] (k-softmaxed, transposed)
__device__ __align__(16) __nv_bfloat16 g_KsT_lo [C_ * SA_];
__device__ __align__(16) __nv_bfloat16 g_qT_hi  [HW_ * C_];   // [hw][c]
__device__ __align__(16) __nv_bfloat16 g_qT_lo  [HW_ * C_];
__device__ __align__(16) __nv_bfloat16 g_QsT_hi [HW_ * C_];   // [hw][o]
__device__ __align__(16) __nv_bfloat16 g_QsT_lo [HW_ * C_];
__device__ __align__(16) __nv_bfloat16 g_Wq_hi[C_ * C_], g_Wq_lo[C_ * C_];
__device__ __align__(16) __nv_bfloat16 g_Wk_hi[C_ * C_], g_Wk_lo[C_ * C_];
__device__ __align__(16) __nv_bfloat16 g_Wv_hi[C_ * C_], g_Wv_lo[C_ * C_];
__device__ __align__(16) __nv_bfloat16 g_T2T_hi[C_ * C_], g_T2T_lo[C_ * C_];
__device__ __align__(16) __nv_bfloat16 g_G_hi [C_ * C_], g_G_lo [C_ * C_];
__device__ __align__(16) float g_Qlog[C_ * HW_];   // q logits -> softmaxed in place
__device__ __align__(16) float g_T2  [C_ * C_];    // split-K accumulator [a][o]

// ---------------------------------------------------------------------------
// PTX helpers (compute_100-safe)
// ---------------------------------------------------------------------------
__device__ __forceinline__ uint32_t smem_u32(const void* p) {
    uint32_t a;
    asm("{ .reg .u64 t; cvta.to.shared.u64 t, %1; cvt.u32.u64 %0, t; }" : "=r"(a) : "l"(p));
    return a;
}
__device__ __forceinline__ void cp16(uint32_t dst, const void* src) {
    asm volatile("cp.async.cg.shared.global [%0], [%1], 16;" :: "r"(dst), "l"(src));
}
__device__ __forceinline__ void cp_commit() {
    asm volatile("cp.async.commit_group;" ::: "memory");
}
template<int N>
__device__ __forceinline__ void cp_wait() {
    asm volatile("cp.async.wait_group %0;" :: "n"(N) : "memory");
}
__device__ __forceinline__ void ldm_x4(uint32_t* r, uint32_t addr) {
    asm volatile("ldmatrix.sync.aligned.m8n8.x4.shared.b16 {%0,%1,%2,%3}, [%4];"
                 : "=r"(r[0]), "=r"(r[1]), "=r"(r[2]), "=r"(r[3]) : "r"(addr));
}
__device__ __forceinline__ void mma16816(float* c, const uint32_t* a, const uint32_t* b) {
    asm volatile(
        "mma.sync.aligned.m16n8k16.row.col.f32.bf16.bf16.f32 "
        "{%0,%1,%2,%3}, {%4,%5,%6,%7}, {%8,%9}, {%0,%1,%2,%3};"
        : "+f"(c[0]), "+f"(c[1]), "+f"(c[2]), "+f"(c[3])
        : "r"(a[0]), "r"(a[1]), "r"(a[2]), "r"(a[3]), "r"(b[0]), "r"(b[1]));
}
__device__ __forceinline__ void split_bf16(float v, __nv_bfloat16& h, __nv_bfloat16& l) {
    h = __float2bfloat16(v);
    l = __float2bfloat16(v - __bfloat162float(h));
}

// ---------------------------------------------------------------------------
// fp32 -> bf16 hi/lo split (no transpose), grid-stride
// ---------------------------------------------------------------------------
__global__ void conv_hilo_kernel(const float* __restrict__ src, int srcLd,
                                 __nv_bfloat16* __restrict__ hi,
                                 __nv_bfloat16* __restrict__ lo,
                                 int dstLd, int rows, int cols)
{
    int colq = cols >> 2;
    int total = rows * colq;
    for (int idx = blockIdx.x * blockDim.x + threadIdx.x; idx < total;
         idx += gridDim.x * blockDim.x) {
        int r = idx / colq;
        int c4 = (idx - r * colq) << 2;
        float4 v = *reinterpret_cast<const float4*>(src + (size_t)r * srcLd + c4);
        float vv[4] = {v.x, v.y, v.z, v.w};
        __nv_bfloat16 h[4], l[4];
#pragma unroll
        for (int i = 0; i < 4; i++) split_bf16(vv[i], h[i], l[i]);
        uint32_t ph  = (uint32_t)__bfloat16_as_ushort(h[0]) | ((uint32_t)__bfloat16_as_ushort(h[1]) << 16);
        uint32_t ph2 = (uint32_t)__bfloat16_as_ushort(h[2]) | ((uint32_t)__bfloat16_as_ushort(h[3]) << 16);
        uint32_t pl  = (uint32_t)__bfloat16_as_ushort(l[0]) | ((uint32_t)__bfloat16_as_ushort(l[1]) << 16);
        uint32_t pl2 = (uint32_t)__bfloat16_as_ushort(l[2]) | ((uint32_t)__bfloat16_as_ushort(l[3]) << 16);
        *reinterpret_cast<uint2*>(hi + (size_t)r * dstLd + c4) = make_uint2(ph, ph2);
        *reinterpret_cast<uint2*>(lo + (size_t)r * dstLd + c4) = make_uint2(pl, pl2);
    }
}

// 3 weight matrices (256x256) in one launch via grid.z
__global__ void convW3_kernel(const float* __restrict__ s0, const float* __restrict__ s1,
                              const float* __restrict__ s2,
                              __nv_bfloat16* __restrict__ h0, __nv_bfloat16* __restrict__ l0,
                              __nv_bfloat16* __restrict__ h1, __nv_bfloat16* __restrict__ l1,
                              __nv_bfloat16* __restrict__ h2, __nv_bfloat16* __restrict__ l2)
{
    const float* src = (blockIdx.z == 0) ? s0 : (blockIdx.z == 1) ? s1 : s2;
    __nv_bfloat16* hi = (blockIdx.z == 0) ? h0 : (blockIdx.z == 1) ? h1 : h2;
    __nv_bfloat16* lo = (blockIdx.z == 0) ? l0 : (blockIdx.z == 1) ? l1 : l2;
    int idx = blockIdx.x * blockDim.x + threadIdx.x;   // 16384 float4 slots
    float4 v = *reinterpret_cast<const float4*>(src + idx * 4);
    float vv[4] = {v.x, v.y, v.z, v.w};
    __nv_bfloat16 h[4], l[4];
#pragma unroll
    for (int i = 0; i < 4; i++) split_bf16(vv[i], h[i], l[i]);
    uint32_t ph  = (uint32_t)__bfloat16_as_ushort(h[0]) | ((uint32_t)__bfloat16_as_ushort(h[1]) << 16);
    uint32_t ph2 = (uint32_t)__bfloat16_as_ushort(h[2]) | ((uint32_t)__bfloat16_as_ushort(h[3]) << 16);
    uint32_t pl  = (uint32_t)__bfloat16_as_ushort(l[0]) | ((uint32_t)__bfloat16_as_ushort(l[1]) << 16);
    uint32_t pl2 = (uint32_t)__bfloat16_as_ushort(l[2]) | ((uint32_t)__bfloat16_as_ushort(l[3]) << 16);
    *reinterpret_cast<uint2*>(hi + idx * 4) = make_uint2(ph, ph2);
    *reinterpret_cast<uint2*>(lo + idx * 4) = make_uint2(pl, pl2);
}

// ---------------------------------------------------------------------------
// fp32 [R][Csrc] -> bf16 hi/lo [Csrc][R] (transpose + split), vectorized stores
// grid = (srcCols/32, srcRows/32), block = (32, 8)
// ---------------------------------------------------------------------------
__global__ void convT_kernel(const float* __restrict__ src, int srcLd,
                             __nv_bfloat16* __restrict__ hi,
                             __nv_bfloat16* __restrict__ lo, int dstLd)
{
    __shared__ float t[32][33];
    int c0 = blockIdx.x * 32, r0 = blockIdx.y * 32;
    int tx = threadIdx.x, ty = threadIdx.y;
#pragma unroll
    for (int i = 0; i < 4; i++)
        t[ty + i * 8][tx] = src[(size_t)(r0 + ty + i * 8) * srcLd + c0 + tx];
    __syncthreads();
    int tid = ty * 32 + tx;
    int c = tid >> 3;          // 0..31 dst row (src col)
    int r = (tid & 7) * 4;     // dst col group (src row)
    __nv_bfloat16 h[4], l[4];
#pragma unroll
    for (int k = 0; k < 4; k++) split_bf16(t[r + k][c], h[k], l[k]);
    uint32_t ph  = (uint32_t)__bfloat16_as_ushort(h[0]) | ((uint32_t)__bfloat16_as_ushort(h[1]) << 16);
    uint32_t ph2 = (uint32_t)__bfloat16_as_ushort(h[2]) | ((uint32_t)__bfloat16_as_ushort(h[3]) << 16);
    uint32_t pl  = (uint32_t)__bfloat16_as_ushort(l[0]) | ((uint32_t)__bfloat16_as_ushort(l[1]) << 16);
    uint32_t pl2 = (uint32_t)__bfloat16_as_ushort(l[2]) | ((uint32_t)__bfloat16_as_ushort(l[3]) << 16);
    size_t o = (size_t)(c0 + c) * dstLd + r0 + r;
    *reinterpret_cast<uint2*>(hi + o) = make_uint2(ph, ph2);
    *reinterpret_cast<uint2*>(lo + o) = make_uint2(pl, pl2);
}

// ---------------------------------------------------------------------------
// Generic tensor-core GEMM, bf16x3 split, BM=BN=128, BK=32, 4-stage cp.async.
//   D[m,n] (+)= sum_k A[m,k]*B[n,k]
// EPI: 0 fp32 store | 2 fp32 atomicAdd | 3 bf16 hi/lo split store
// ---------------------------------------------------------------------------
static constexpr int ARR_BYTES   = 128 * 80;
static constexpr int STAGE_BYTES = 4 * ARR_BYTES;      // 40960
static constexpr int GEMM_SMEM   = 4 * STAGE_BYTES;    // 163840

__device__ __forceinline__ void load_stage(uint32_t sb, int stage,
    const __nv_bfloat16* __restrict__ Ah, const __nv_bfloat16* __restrict__ Al,
    int aLd, int m0,
    const __nv_bfloat16* __restrict__ Bh, const __nv_bfloat16* __restrict__ Bl,
    int bLd, int n0, int kOff, int tid)
{
    uint32_t base = sb + stage * STAGE_BYTES;
#pragma unroll
    for (int i = 0; i < 8; i++) {
        int idx = tid + i * 256;
        int arr = idx >> 9;
        int rem = idx & 511;
        int row = rem >> 2;
        int ch  = rem & 3;
        const __nv_bfloat16* g;
        int ld, rb;
        if (arr == 0)      { g = Ah; ld = aLd; rb = m0; }
        else if (arr == 1) { g = Al; ld = aLd; rb = m0; }
        else if (arr == 2) { g = Bh; ld = bLd; rb = n0; }
        else               { g = Bl; ld = bLd; rb = n0; }
        cp16(base + arr * ARR_BYTES + row * 80 + ch * 16,
             g + (size_t)(rb + row) * ld + kOff + ch * 8);
    }
}

template<int EPI>
__global__ void __launch_bounds__(256, 1) gemm_mma_kernel(
    const __nv_bfloat16* __restrict__ Ah, const __nv_bfloat16* __restrict__ Al, int aLd,
    const __nv_bfloat16* __restrict__ Bh, const __nv_bfloat16* __restrict__ Bl, int bLd,
    float* __restrict__ out, int outLd, int kPerCta,
    __nv_bfloat16* __restrict__ ohi, __nv_bfloat16* __restrict__ olo)
{
    extern __shared__ char smem[];
    uint32_t sb = smem_u32(smem);
    const int tid  = threadIdx.x;
    const int wid  = tid >> 5;
    const int lane = tid & 31;
    const int m0 = blockIdx.y * 128;
    const int n0 = blockIdx.x * 128;
    const int kStart = blockIdx.z * kPerCta;
    const int nChunks = kPerCta >> 5;

    const int wm = wid >> 2, wn = wid & 3;
    const int mBase = wm * 64, nBase = wn * 32;
    const int g = lane >> 2, t = lane & 3;
    const int mat = lane >> 3, r = lane & 7;

    const uint32_t aOff = (uint32_t)(mBase + (mat & 1) * 8 + r) * 80 + (mat >> 1) * 16;
    const uint32_t bOff = 2 * ARR_BYTES + (uint32_t)(nBase + (mat >> 1) * 8 + r) * 80 + (mat & 1) * 16;

    float acc[4][4][4];
#pragma unroll
    for (int i = 0; i < 4; i++)
#pragma unroll
        for (int j = 0; j < 4; j++)
#pragma unroll
            for (int e = 0; e < 4; e++) acc[i][j][e] = 0.0f;

#pragma unroll
    for (int s = 0; s < 3; s++) {
        if (s < nChunks) {
            load_stage(sb, s, Ah, Al, aLd, m0, Bh, Bl, bLd, n0, kStart + s * 32, tid);
            cp_commit();
        }
    }

    for (int ch = 0; ch < nChunks; ch++) {
        int allow = nChunks - 1 - ch;
        if (allow >= 2)      cp_wait<2>();
        else if (allow == 1) cp_wait<1>();
        else                 cp_wait<0>();
        __syncthreads();
        int nx = ch + 3;
        if (nx < nChunks) {
            load_stage(sb, nx & 3, Ah, Al, aLd, m0, Bh, Bl, bLd, n0, kStart + nx * 32, tid);
            cp_commit();
        }

        const uint32_t stageBase = sb + (ch & 3) * STAGE_BYTES;
#pragma unroll
        for (int kk = 0; kk < 2; kk++) {
            const uint32_t colOff = kk * 32;
            uint32_t bh[8], bl[8], ah[4][4], al[4][4];
#pragma unroll
            for (int p = 0; p < 2; p++) {
                ldm_x4(&bh[p * 4], stageBase + bOff + p * 1280 + colOff);
                ldm_x4(&bl[p * 4], stageBase + ARR_BYTES + bOff + p * 1280 + colOff);
            }
#pragma unroll
            for (int mt = 0; mt < 4; mt++) {
                ldm_x4(ah[mt], stageBase + aOff + mt * 1280 + colOff);
                ldm_x4(al[mt], stageBase + ARR_BYTES + aOff + mt * 1280 + colOff);
            }
#pragma unroll
            for (int mt = 0; mt < 4; mt++) {
#pragma unroll
                for (int nt = 0; nt < 4; nt++) {
                    const uint32_t* bhp = &bh[(nt >> 1) * 4 + (nt & 1) * 2];
                    const uint32_t* blp = &bl[(nt >> 1) * 4 + (nt & 1) * 2];
                    mma16816(acc[mt][nt], ah[mt], bhp);
                    mma16816(acc[mt][nt], ah[mt], blp);
                    mma16816(acc[mt][nt], al[mt], bhp);
                }
            }
        }
    }

#pragma unroll
    for (int mt = 0; mt < 4; mt++) {
#pragma unroll
        for (int nt = 0; nt < 4; nt++) {
            int row = m0 + mBase + mt * 16 + g;
            int col = n0 + nBase + nt * 8 + 2 * t;
            if (EPI == 0) {
                *reinterpret_cast<float2*>(out + (size_t)row * outLd + col) =
                    make_float2(acc[mt][nt][0], acc[mt][nt][1]);
                *reinterpret_cast<float2*>(out + (size_t)(row + 8) * outLd + col) =
                    make_float2(acc[mt][nt][2], acc[mt][nt][3]);
            } else if (EPI == 2) {
                float* p0 = out + (size_t)row * outLd + col;
                float* p1 = out + (size_t)(row + 8) * outLd + col;
                atomicAdd(p0,     acc[mt][nt][0]);
                atomicAdd(p0 + 1, acc[mt][nt][1]);
                atomicAdd(p1,     acc[mt][nt][2]);
                atomicAdd(p1 + 1, acc[mt][nt][3]);
            } else {  // EPI == 3: bf16 hi/lo split store
#pragma unroll
                for (int hh = 0; hh < 2; hh++) {
                    __nv_bfloat16 h0, l0, h1, l1;
                    split_bf16(acc[mt][nt][hh * 2 + 0], h0, l0);
                    split_bf16(acc[mt][nt][hh * 2 + 1], h1, l1);
                    size_t o = (size_t)(row + hh * 8) * outLd + col;
                    *reinterpret_cast<uint32_t*>(ohi + o) =
                        (uint32_t)__bfloat16_as_ushort(h0) | ((uint32_t)__bfloat16_as_ushort(h1) << 16);
                    *reinterpret_cast<uint32_t*>(olo + o) =
                        (uint32_t)__bfloat16_as_ushort(l0) | ((uint32_t)__bfloat16_as_ushort(l1) << 16);
                }
            }
        }
    }
}

// ---------------------------------------------------------------------------
// Fused GEMM1 + k-softmax + transpose + split:
//   Klog[j][o] = keyT[j][:] . Wk[o][:]   (BM=128 j, BN=256 o, K=256)
//   then per-row softmax over all 256 o, output KsT_hi/lo [o][j] bf16.
// 2-stage cp.async, 8 warps (2 x 4), warp tile 64x64.
// ---------------------------------------------------------------------------
static constexpr int KSM_A_HI = 0;
static constexpr int KSM_A_LO = 128 * 80;            // 10240
static constexpr int KSM_B_HI = 2 * 128 * 80;        // 20480
static constexpr int KSM_B_LO = KSM_B_HI + 256 * 80; // 40960
static constexpr int KSM_STAGE = KSM_B_LO + 256 * 80; // 61440
static constexpr int KSM_SMEM  = 2 * KSM_STAGE;       // 122880
static constexpr int KSM_STG_LO = 128 * 136 * 2;      // 34816 (lo staging offset)
static constexpr int KSM_RED    = 73728;              // reduction buffers offset

__device__ __forceinline__ void ksm_load_stage(uint32_t sb, int stage,
    const __nv_bfloat16* __restrict__ Ah, const __nv_bfloat16* __restrict__ Al, int j0,
    const __nv_bfloat16* __restrict__ Bh, const __nv_bfloat16* __restrict__ Bl,
    int kOff, int tid)
{
    uint32_t base = sb + stage * KSM_STAGE;
#pragma unroll
    for (int i = 0; i < 12; i++) {
        int idx = tid + i * 256;          // 0..3071
        const __nv_bfloat16* g;
        int row, arrOff, rb;
        if (idx < 512)       { g = Ah; row = idx >> 2;          arrOff = KSM_A_HI; rb = j0; }
        else if (idx < 1024) { g = Al; row = (idx - 512) >> 2;  arrOff = KSM_A_LO; rb = j0; }
        else if (idx < 2048) { g = Bh; row = (idx - 1024) >> 2; arrOff = KSM_B_HI; rb = 0; }
        else                 { g = Bl; row = (idx - 2048) >> 2; arrOff = KSM_B_LO; rb = 0; }
        int ch = idx & 3;
        cp16(base + arrOff + row * 80 + ch * 16,
             g + (size_t)(rb + row) * C_ + kOff + ch * 8);
    }
}

__global__ void __launch_bounds__(256, 1) gemm_ksm_kernel(
    const __nv_bfloat16* __restrict__ Ah, const __nv_bfloat16* __restrict__ Al,
    const __nv_bfloat16* __restrict__ Bh, const __nv_bfloat16* __restrict__ Bl,
    __nv_bfloat16* __restrict__ KsT_hi, __nv_bfloat16* __restrict__ KsT_lo)
{
    extern __shared__ char smem[];
    uint32_t sb = smem_u32(smem);
    const int tid  = threadIdx.x;
    const int wid  = tid >> 5;
    const int lane = tid & 31;
    const int j0 = blockIdx.x * 128;

    const int wm = wid >> 2, wn = wid & 3;
    const int mBase = wm * 64, nBase = wn * 64;
    const int g = lane >> 2, t = lane & 3;
    const int mat = lane >> 3, r = lane & 7;

    const uint32_t aOffHi = KSM_A_HI + (uint32_t)(mBase + (mat & 1) * 8 + r) * 80 + (mat >> 1) * 16;
    const uint32_t bOffHi = KSM_B_HI + (uint32_t)(nBase + (mat >> 1) * 8 + r) * 80 + (mat & 1) * 16;

    float acc[4][8][4];
#pragma unroll
    for (int i = 0; i < 4; i++)
#pragma unroll
        for (int j = 0; j < 8; j++)
#pragma unroll
            for (int e = 0; e < 4; e++) acc[i][j][e] = 0.0f;

    ksm_load_stage(sb, 0, Ah, Al, j0, Bh, Bl, 0, tid);
    cp_commit();

    const int nChunks = 8;   // K=256
    for (int ch = 0; ch < nChunks; ch++) {
        if (ch + 1 < nChunks) {
            ksm_load_stage(sb, (ch + 1) & 1, Ah, Al, j0, Bh, Bl, (ch + 1) * 32, tid);
            cp_commit();
            cp_wait<1>();
        } else {
            cp_wait<0>();
        }
        __syncthreads();

        const uint32_t stageBase = sb + (ch & 1) * KSM_STAGE;
#pragma unroll
        for (int kk = 0; kk < 2; kk++) {
            const uint32_t colOff = kk * 32;
            uint32_t ah[4][4], al[4][4];
#pragma unroll
            for (int mt = 0; mt < 4; mt++) {
                ldm_x4(ah[mt], stageBase + aOffHi + mt * 1280 + colOff);
                ldm_x4(al[mt], stageBase + KSM_A_LO + aOffHi + mt * 1280 + colOff);
            }
#pragma unroll
            for (int ph = 0; ph < 2; ph++) {
                uint32_t bh8[8], bl8[8];
#pragma unroll
                for (int pl = 0; pl < 2; pl++) {
                    ldm_x4(&bh8[pl * 4], stageBase + bOffHi + (ph * 2 + pl) * 1280 + colOff);
                    ldm_x4(&bl8[pl * 4], stageBase + (KSM_B_LO - KSM_B_HI) + bOffHi + (ph * 2 + pl) * 1280 + colOff);
                }
#pragma unroll
                for (int mt = 0; mt < 4; mt++) {
#pragma unroll
                    for (int l = 0; l < 4; l++) {
                        const uint32_t* bhp = &bh8[(l >> 1) * 4 + (l & 1) * 2];
                        const uint32_t* blp = &bl8[(l >> 1) * 4 + (l & 1) * 2];
                        int nt = ph * 4 + l;
                        mma16816(acc[mt][nt], ah[mt], bhp);
                        mma16816(acc[mt][nt], ah[mt], blp);
                        mma16816(acc[mt][nt], al[mt], bhp);
                    }
                }
            }
        }
        __syncthreads();
    }

    // ---------------- fused epilogue: row softmax over 256 cols ------------
    float* redA = reinterpret_cast<float*>(smem + KSM_RED);
    float* redB = redA + 512;

    // 1) row max
    float rmax[4][2];
#pragma unroll
    for (int mt = 0; mt < 4; mt++) {
#pragma unroll
        for (int h = 0; h < 2; h++) {
            float m = -1e30f;
#pragma unroll
            for (int nt = 0; nt < 8; nt++) {
                m = fmaxf(m, acc[mt][nt][h * 2 + 0]);
                m = fmaxf(m, acc[mt][nt][h * 2 + 1]);
            }
            m = fmaxf(m, __shfl_xor_sync(0xffffffffu, m, 1));
            m = fmaxf(m, __shfl_xor_sync(0xffffffffu, m, 2));
            if (t == 0) redA[(mBase + mt * 16 + h * 8 + g) * 4 + wn] = m;
        }
    }
    __syncthreads();
#pragma unroll
    for (int mt = 0; mt < 4; mt++)
#pragma unroll
        for (int h = 0; h < 2; h++) {
            int row = mBase + mt * 16 + h * 8 + g;
            float m = fmaxf(fmaxf(redA[row * 4], redA[row * 4 + 1]),
                            fmaxf(redA[row * 4 + 2], redA[row * 4 + 3]));
            rmax[mt][h] = m * INV_TEMP;
        }

    // 2) exp + row sum
    float rinv[4][2];
#pragma unroll
    for (int mt = 0; mt < 4; mt++) {
#pragma unroll
        for (int h = 0; h < 2; h++) {
            float s = 0.0f;
#pragma unroll
            for (int nt = 0; nt < 8; nt++) {
#pragma unroll
                for (int e2 = 0; e2 < 2; e2++) {
                    float w = __expf(acc[mt][nt][h * 2 + e2] * INV_TEMP - rmax[mt][h]);
                    acc[mt][nt][h * 2 + e2] = w;
                    s += w;
                }
            }
            s += __shfl_xor_sync(0xffffffffu, s, 1);
            s += __shfl_xor_sync(0xffffffffu, s, 2);
            if (t == 0) redB[(mBase + mt * 16 + h * 8 + g) * 4 + wn] = s;
        }
    }
    __syncthreads();
#pragma unroll
    for (int mt = 0; mt < 4; mt++)
#pragma unroll
        for (int h = 0; h < 2; h++) {
            int row = mBase + mt * 16 + h * 8 + g;
            float s = redB[row * 4] + redB[row * 4 + 1] + redB[row * 4 + 2] + redB[row * 4 + 3];
            rinv[mt][h] = 1.0f / s;
        }

    // 3) transposed store via smem staging, two 128-o passes
#pragma unroll
    for (int p = 0; p < 2; p++) {
        if ((wn >> 1) == p) {
            int oBase = (wn & 1) * 64;
#pragma unroll
            for (int mt = 0; mt < 4; mt++) {
#pragma unroll
                for (int h = 0; h < 2; h++) {
                    int jl = mBase + mt * 16 + h * 8 + g;
#pragma unroll
                    for (int nt = 0; nt < 8; nt++) {
#pragma unroll
                        for (int e2 = 0; e2 < 2; e2++) {
                            int ol = oBase + nt * 8 + 2 * t + e2;
                            float w = acc[mt][nt][h * 2 + e2] * rinv[mt][h];
                            __nv_bfloat16 hh, ll;
                            split_bf16(w, hh, ll);
                            *reinterpret_cast<__nv_bfloat16*>(smem + (ol * 136 + jl) * 2) = hh;
                            *reinterpret_cast<__nv_bfloat16*>(smem + KSM_STG_LO + (ol * 136 + jl) * 2) = ll;
                        }
                    }
                }
            }
        }
        __syncthreads();
#pragma unroll
        for (int it = 0; it < 8; it++) {
            int idx = tid + it * 256;
            int row = idx >> 4, seg = idx & 15;
            uint4 vh = *reinterpret_cast<uint4*>(smem + (row * 136 + seg * 8) * 2);
            uint4 vl = *reinterpret_cast<uint4*>(smem + KSM_STG_LO + (row * 136 + seg * 8) * 2);
            size_t o = (size_t)(p * 128 + row) * SA_ + j0 + seg * 8;
            *reinterpret_cast<uint4*>(KsT_hi + o) = vh;
            *reinterpret_cast<uint4*>(KsT_lo + o) = vl;
        }
        __syncthreads();
    }
}

// ---------------------------------------------------------------------------
// q softmax (rows of 4096)
// ---------------------------------------------------------------------------
template<int NT, int NE>
__global__ void __launch_bounds__(NT) softmax_row_kernel(float* __restrict__ data, int cols, float scale)
{
    float* row = data + (size_t)blockIdx.x * cols;
    __shared__ float sred[32];
    const int tid = threadIdx.x;
    const int lane = tid & 31;
    const int wid = tid >> 5;
    constexpr int NW = NT / 32;

    float v[NE];
    float m = -1e30f;
#pragma unroll
    for (int e = 0; e < NE; e++) {
        v[e] = row[tid + e * NT] * scale;
        m = fmaxf(m, v[e]);
    }
#pragma unroll
    for (int o = 16; o > 0; o >>= 1) m = fmaxf(m, __shfl_xor_sync(0xffffffffu, m, o));
    if (lane == 0) sred[wid] = m;
    __syncthreads();
    if (wid == 0) {
        float tv = (lane < NW) ? sred[lane] : -1e30f;
#pragma unroll
        for (int o = 16; o > 0; o >>= 1) tv = fmaxf(tv, __shfl_xor_sync(0xffffffffu, tv, o));
        if (lane == 0) sred[0] = tv;
    }
    __syncthreads();
    m = sred[0];
    __syncthreads();

    float sum = 0.0f;
#pragma unroll
    for (int e = 0; e < NE; e++) {
        v[e] = __expf(v[e] - m);
        sum += v[e];
    }
#pragma unroll
    for (int o = 16; o > 0; o >>= 1) sum += __shfl_xor_sync(0xffffffffu, sum, o);
    if (lane == 0) sred[wid] = sum;
    __syncthreads();
    if (wid == 0) {
        float tv = (lane < NW) ? sred[lane] : 0.0f;
#pragma unroll
        for (int o = 16; o > 0; o >>= 1) tv += __shfl_xor_sync(0xffffffffu, tv, o);
        if (lane == 0) sred[0] = tv;
    }
    __syncthreads();
    float inv = 1.0f / sred[0];
#pragma unroll
    for (int e = 0; e < NE; e++)
        row[tid + e * NT] = v[e] * inv;
}

__global__ void zero_kernel(float* __restrict__ p, int n)
{
    int i = blockIdx.x * blockDim.x + threadIdx.x;
    if (i < n) p[i] = 0.0f;
}

// ---------------------------------------------------------------------------
// Launch
// ---------------------------------------------------------------------------
extern "C" void kernel_launch(void* const* d_in, const int* in_sizes, int n_in,
                              void* d_out, int out_size)
{
    (void)in_sizes; (void)n_in; (void)out_size;
    const float* query = (const float*)d_in[0]; // (C, HW)
    const float* key   = (const float*)d_in[1]; // (C, S)
    const float* value = (const float*)d_in[2]; // (C, S)
    const float* Wq    = (const float*)d_in[3]; // (C, C)
    const float* Wk    = (const float*)d_in[4];
    const float* Wv    = (const float*)d_in[5];
    float* out = (float*)d_out;                 // (C, HW)

    cudaFuncSetAttribute(gemm_mma_kernel<0>, cudaFuncAttributeMaxDynamicSharedMemorySize, GEMM_SMEM);
    cudaFuncSetAttribute(gemm_mma_kernel<2>, cudaFuncAttributeMaxDynamicSharedMemorySize, GEMM_SMEM);
    cudaFuncSetAttribute(gemm_mma_kernel<3>, cudaFuncAttributeMaxDynamicSharedMemorySize, GEMM_SMEM);
    cudaFuncSetAttribute(gemm_ksm_kernel, cudaFuncAttributeMaxDynamicSharedMemorySize, KSM_SMEM);

    __nv_bfloat16 *keyT_hi, *keyT_lo, *val_hi, *val_lo, *KsT_hi, *KsT_lo;
    __nv_bfloat16 *qT_hi, *qT_lo, *QsT_hi, *QsT_lo;
    __nv_bfloat16 *Wq_hi, *Wq_lo, *Wk_hi, *Wk_lo, *Wv_hi, *Wv_lo;
    __nv_bfloat16 *T2T_hi, *T2T_lo, *G_hi, *G_lo;
    float *Qlog, *T2;
    cudaGetSymbolAddress((void**)&keyT_hi, g_keyT_hi);
    cudaGetSymbolAddress((void**)&keyT_lo, g_keyT_lo);
    cudaGetSymbolAddress((void**)&val_hi,  g_val_hi);
    cudaGetSymbolAddress((void**)&val_lo,  g_val_lo);
    cudaGetSymbolAddress((void**)&KsT_hi,  g_KsT_hi);
    cudaGetSymbolAddress((void**)&KsT_lo,  g_KsT_lo);
    cudaGetSymbolAddress((void**)&qT_hi,   g_qT_hi);
    cudaGetSymbolAddress((void**)&qT_lo,   g_qT_lo);
    cudaGetSymbolAddress((void**)&QsT_hi,  g_QsT_hi);
    cudaGetSymbolAddress((void**)&QsT_lo,  g_QsT_lo);
    cudaGetSymbolAddress((void**)&Wq_hi,   g_Wq_hi);
    cudaGetSymbolAddress((void**)&Wq_lo,   g_Wq_lo);
    cudaGetSymbolAddress((void**)&Wk_hi,   g_Wk_hi);
    cudaGetSymbolAddress((void**)&Wk_lo,   g_Wk_lo);
    cudaGetSymbolAddress((void**)&Wv_hi,   g_Wv_hi);
    cudaGetSymbolAddress((void**)&Wv_lo,   g_Wv_lo);
    cudaGetSymbolAddress((void**)&T2T_hi,  g_T2T_hi);
    cudaGetSymbolAddress((void**)&T2T_lo,  g_T2T_lo);
    cudaGetSymbolAddress((void**)&G_hi,    g_G_hi);
    cudaGetSymbolAddress((void**)&G_lo,    g_G_lo);
    cudaGetSymbolAddress((void**)&Qlog,    g_Qlog);
    cudaGetSymbolAddress((void**)&T2,      g_T2);

    // ---- conversions ----
    convW3_kernel<<<dim3(64, 1, 3), 256>>>(Wq, Wk, Wv, Wq_hi, Wq_lo, Wk_hi, Wk_lo, Wv_hi, Wv_lo);
    convT_kernel<<<dim3(SA_ / 32, C_ / 32), dim3(32, 8)>>>(key + S0_, S_, keyT_hi, keyT_lo, C_);
    conv_hilo_kernel<<<2560, 256>>>(value + S0_, S_, val_hi, val_lo, SA_, C_, SA_);
    convT_kernel<<<dim3(HW_ / 32, C_ / 32), dim3(32, 8)>>>(query, HW_, qT_hi, qT_lo, C_);

    // ---- GEMM1 + fused k-softmax + transpose + split ----
    gemm_ksm_kernel<<<SA_ / 128, 256, KSM_SMEM>>>(keyT_hi, keyT_lo, Wk_hi, Wk_lo, KsT_hi, KsT_lo);

    // ---- GEMM2: Qlog[o][hw] = Wq[o][:] . qT[hw][:] ----
    gemm_mma_kernel<0><<<dim3(HW_ / 128, C_ / 128, 1), 256, GEMM_SMEM>>>(
        Wq_hi, Wq_lo, C_, qT_hi, qT_lo, C_, Qlog, HW_, C_, nullptr, nullptr);

    // ---- q softmax over hw, then transpose/split -> QsT ----
    softmax_row_kernel<256, 16><<<C_, 256>>>(Qlog, HW_, INV_TEMP);
    convT_kernel<<<dim3(HW_ / 32, C_ / 32), dim3(32, 8)>>>(Qlog, HW_, QsT_hi, QsT_lo, C_);

    // ---- GEMM3: T2[a][o] = sum_j val[a][j]*Ks[j][o], split-K 32, atomic ----
    zero_kernel<<<(C_ * C_ + 255) / 256, 256>>>(T2, C_ * C_);
    gemm_mma_kernel<2><<<dim3(C_ / 128, C_ / 128, 32), 256, GEMM_SMEM>>>(
        val_hi, val_lo, SA_, KsT_hi, KsT_lo, SA_, T2, C_, SA_ / 32, nullptr, nullptr);

    // T2 -> T2T [o][a] bf16 hi/lo
    convT_kernel<<<dim3(C_ / 32, C_ / 32), dim3(32, 8)>>>(T2, C_, T2T_hi, T2T_lo, C_);

    // ---- GEMM4: G[c][o] = sum_a Wv[c][a]*T2T[o][a], direct hi/lo output ----
    gemm_mma_kernel<3><<<dim3(C_ / 128, C_ / 128, 1), 256, GEMM_SMEM>>>(
        Wv_hi, Wv_lo, C_, T2T_hi, T2T_lo, C_, nullptr, C_, C_, G_hi, G_lo);

    // ---- GEMM5: out[c][hw] = sum_o G[c][o]*Qs[o][hw] ----
    gemm_mma_kernel<0><<<dim3(HW_ / 128, C_ / 128, 1), 256, GEMM_SMEM>>>(
        G_hi, G_lo, C_, QsT_hi, QsT_lo, C_, out, HW_, C_, nullptr, nullptr);
}

// round 5
// speedup vs baseline: 1.0748x; 1.0748x over previous
#include <cuda_runtime.h>
#include <cuda_bf16.h>
#include <cstdint>

// ---------------------------------------------------------------------------
// Problem constants (B=1)
// ---------------------------------------------------------------------------
static constexpr int C_   = 256;
static constexpr int HW_  = 4096;     // 64*64
static constexpr int S_   = 32768;    // 8*64*64
static constexpr int SA_  = 20480;    // 5*64*64 active (last 5 frames)
static constexpr int S0_  = S_ - SA_; // 12288
static constexpr float INV_TEMP = 10.0f;

// ---------------------------------------------------------------------------
// Device scratch
// ---------------------------------------------------------------------------
__device__ __align__(16) __nv_bfloat16 g_Ks_hi [SA_ * C_];   // [j][o]  (k-softmaxed)
__device__ __align__(16) __nv_bfloat16 g_Ks_lo [SA_ * C_];
__device__ __align__(16) __nv_bfloat16 g_Qs_hi [C_ * HW_];   // [o][hw] (q-softmaxed)
__device__ __align__(16) __nv_bfloat16 g_Qs_lo [C_ * HW_];
__device__ __align__(16) __nv_bfloat16 g_Wq_hi[C_ * C_], g_Wq_lo[C_ * C_];
__device__ __align__(16) __nv_bfloat16 g_Wk_hi[C_ * C_], g_Wk_lo[C_ * C_];
__device__ __align__(16) __nv_bfloat16 g_Wv_hi[C_ * C_], g_Wv_lo[C_ * C_];
__device__ __align__(16) __nv_bfloat16 g_G_hi [C_ * C_], g_G_lo [C_ * C_];
__device__ __align__(16) float g_Qlog[C_ * HW_];   // q logits
__device__ __align__(16) float g_T2  [C_ * C_];    // split-K accumulator [a][o]

// ---------------------------------------------------------------------------
// PTX helpers (compute_100-safe)
// ---------------------------------------------------------------------------
__device__ __forceinline__ uint32_t smem_u32(const void* p) {
    uint32_t a;
    asm("{ .reg .u64 t; cvta.to.shared.u64 t, %1; cvt.u32.u64 %0, t; }" : "=r"(a) : "l"(p));
    return a;
}
__device__ __forceinline__ void cp16(uint32_t dst, const void* src) {
    asm volatile("cp.async.cg.shared.global [%0], [%1], 16;" :: "r"(dst), "l"(src));
}
__device__ __forceinline__ void cp_commit() {
    asm volatile("cp.async.commit_group;" ::: "memory");
}
template<int N>
__device__ __forceinline__ void cp_wait() {
    asm volatile("cp.async.wait_group %0;" :: "n"(N) : "memory");
}
__device__ __forceinline__ void ldm_x4(uint32_t* r, uint32_t addr) {
    asm volatile("ldmatrix.sync.aligned.m8n8.x4.shared.b16 {%0,%1,%2,%3}, [%4];"
                 : "=r"(r[0]), "=r"(r[1]), "=r"(r[2]), "=r"(r[3]) : "r"(addr));
}
__device__ __forceinline__ void ldm_x4_t(uint32_t* r, uint32_t addr) {
    asm volatile("ldmatrix.sync.aligned.m8n8.x4.trans.shared.b16 {%0,%1,%2,%3}, [%4];"
                 : "=r"(r[0]), "=r"(r[1]), "=r"(r[2]), "=r"(r[3]) : "r"(addr));
}
__device__ __forceinline__ void mma16816(float* c, const uint32_t* a, const uint32_t* b) {
    asm volatile(
        "mma.sync.aligned.m16n8k16.row.col.f32.bf16.bf16.f32 "
        "{%0,%1,%2,%3}, {%4,%5,%6,%7}, {%8,%9}, {%0,%1,%2,%3};"
        : "+f"(c[0]), "+f"(c[1]), "+f"(c[2]), "+f"(c[3])
        : "r"(a[0]), "r"(a[1]), "r"(a[2]), "r"(a[3]), "r"(b[0]), "r"(b[1]));
}
__device__ __forceinline__ void split_bf16(float v, __nv_bfloat16& h, __nv_bfloat16& l) {
    h = __float2bfloat16(v);
    l = __float2bfloat16(v - __bfloat162float(h));
}
__device__ __forceinline__ uint32_t pack2(__nv_bfloat16 a, __nv_bfloat16 b) {
    return (uint32_t)__bfloat16_as_ushort(a) | ((uint32_t)__bfloat16_as_ushort(b) << 16);
}
// float4 -> hi uint2 / lo uint2
__device__ __forceinline__ void split4(float4 v, uint2& ph, uint2& pl) {
    __nv_bfloat16 h0, l0, h1, l1, h2, l2, h3, l3;
    split_bf16(v.x, h0, l0); split_bf16(v.y, h1, l1);
    split_bf16(v.z, h2, l2); split_bf16(v.w, h3, l3);
    ph = make_uint2(pack2(h0, h1), pack2(h2, h3));
    pl = make_uint2(pack2(l0, l1), pack2(l2, l3));
}

// ---------------------------------------------------------------------------
// 3 weight matrices (256x256) fp32 -> bf16 hi/lo, one launch via grid.z
// ---------------------------------------------------------------------------
__global__ void convW3_kernel(const float* __restrict__ s0, const float* __restrict__ s1,
                              const float* __restrict__ s2,
                              __nv_bfloat16* __restrict__ h0, __nv_bfloat16* __restrict__ l0,
                              __nv_bfloat16* __restrict__ h1, __nv_bfloat16* __restrict__ l1,
                              __nv_bfloat16* __restrict__ h2, __nv_bfloat16* __restrict__ l2)
{
    const float* src = (blockIdx.z == 0) ? s0 : (blockIdx.z == 1) ? s1 : s2;
    __nv_bfloat16* hi = (blockIdx.z == 0) ? h0 : (blockIdx.z == 1) ? h1 : h2;
    __nv_bfloat16* lo = (blockIdx.z == 0) ? l0 : (blockIdx.z == 1) ? l1 : l2;
    int idx = blockIdx.x * blockDim.x + threadIdx.x;   // 16384 float4 slots
    float4 v = *reinterpret_cast<const float4*>(src + idx * 4);
    uint2 ph, pl;
    split4(v, ph, pl);
    *reinterpret_cast<uint2*>(hi + idx * 4) = ph;
    *reinterpret_cast<uint2*>(lo + idx * 4) = pl;
}

// ---------------------------------------------------------------------------
// Generic tensor-core GEMM:  D[m,n] (+)= sum_k A[m,k]*B[n,k], bf16x3 split.
// A: normal layout (K-major rows m), bf16 pair OR fp32 (in-kernel split).
// B: TRANS source layout [k][n] (row-major global), bf16 pair OR fp32.
// BM=BN=128, BK=32, 256 threads, 2-stage cp.async.
// EPI: 0 fp32 store | 2 fp32 atomicAdd | 3 bf16 hi/lo split store
// ---------------------------------------------------------------------------
static constexpr int ABUF = 10240;   // 128 x 80
static constexpr int BBUF = 8704;    // 32 x 272
static constexpr int OFF_B  = 4 * ABUF;            // 40960
static constexpr int OFF_AF = OFF_B + 4 * BBUF;    // 75776
static constexpr int AFSTG  = 18432;               // 128 x 144
static constexpr int BFSTG  = 17408;               // 32 x 544
static constexpr int GEMM_SMEM = OFF_AF + 2 * AFSTG + 2 * BFSTG;  // generous

template<int EPI, bool AF32, bool BF32>
__global__ void __launch_bounds__(256, 1) gemm_uni_kernel(
    const __nv_bfloat16* __restrict__ Ah, const __nv_bfloat16* __restrict__ Al,
    const float* __restrict__ Af, int aLd,
    const __nv_bfloat16* __restrict__ Bh, const __nv_bfloat16* __restrict__ Bl,
    const float* __restrict__ Bf, int bLd,
    float* __restrict__ out, int outLd, int kPerCta,
    __nv_bfloat16* __restrict__ ohi, __nv_bfloat16* __restrict__ olo)
{
    extern __shared__ char smem[];
    uint32_t sb = smem_u32(smem);
    const int tid  = threadIdx.x;
    const int wid  = tid >> 5;
    const int lane = tid & 31;
    const int m0 = blockIdx.y * 128;
    const int n0 = blockIdx.x * 128;
    const int kStart = blockIdx.z * kPerCta;
    const int nChunks = kPerCta >> 5;

    const uint32_t OFF_BF = OFF_AF + (AF32 ? 2 * AFSTG : 0);

    const int wm = wid >> 2, wn = wid & 3;
    const int mBase = wm * 64, nBase = wn * 32;
    const int g = lane >> 2, t = lane & 3;
    const int mat = lane >> 3, r = lane & 7;

    // fragment address bases
    const uint32_t aFrag = (uint32_t)(mBase + (mat & 1) * 8 + r) * 80 + (mat >> 1) * 16;
    const uint32_t bFrag = (uint32_t)((mat & 1) * 8 + r) * 272 + (nBase + (mat >> 1) * 8) * 2;

    float acc[4][4][4];
#pragma unroll
    for (int i = 0; i < 4; i++)
#pragma unroll
        for (int j = 0; j < 4; j++)
#pragma unroll
            for (int e = 0; e < 4; e++) acc[i][j][e] = 0.0f;

    // ---- stage loader ----
    auto load_stage = [&](int st, int kOff) {
#pragma unroll
        for (int i = 0; i < 8; i++) {
            int idx = tid + i * 256;
            if (idx < 1024) {
                if (AF32) {
                    int row = idx >> 3, ch = idx & 7;
                    cp16(sb + OFF_AF + st * AFSTG + row * 144 + ch * 16,
                         Af + (size_t)(m0 + row) * aLd + kOff + ch * 4);
                } else {
                    int hl = idx >> 9, rem = idx & 511;
                    int row = rem >> 2, ch = rem & 3;
                    cp16(sb + (st * 2 + hl) * ABUF + row * 80 + ch * 16,
                         (hl ? Al : Ah) + (size_t)(m0 + row) * aLd + kOff + ch * 8);
                }
            } else {
                int idx2 = idx - 1024;
                if (BF32) {
                    int row = idx2 >> 5, ch = idx2 & 31;
                    cp16(sb + OFF_BF + st * BFSTG + row * 544 + ch * 16,
                         Bf + (size_t)(kOff + row) * bLd + n0 + ch * 4);
                } else {
                    int hl = idx2 >> 9, rem = idx2 & 511;
                    int row = rem >> 4, ch = rem & 15;
                    cp16(sb + OFF_B + (st * 2 + hl) * BBUF + row * 272 + ch * 16,
                         (hl ? Bl : Bh) + (size_t)(kOff + row) * bLd + n0 + ch * 8);
                }
            }
        }
    };

    load_stage(0, kStart);
    cp_commit();

    for (int ch = 0; ch < nChunks; ch++) {
        if (ch + 1 < nChunks) {
            load_stage((ch + 1) & 1, kStart + (ch + 1) * 32);
            cp_commit();
            cp_wait<1>();
        } else {
            cp_wait<0>();
        }
        __syncthreads();

        const int st = ch & 1;
        if (AF32 || BF32) {
            if (AF32) {
#pragma unroll
                for (int it = 0; it < 4; it++) {
                    int slot = tid + it * 256;
                    int row = slot >> 3, c4 = (slot & 7) * 4;
                    float4 v = *reinterpret_cast<const float4*>(smem + OFF_AF + st * AFSTG + row * 144 + c4 * 4);
                    uint2 ph, pl;
                    split4(v, ph, pl);
                    *reinterpret_cast<uint2*>(smem + (st * 2 + 0) * ABUF + row * 80 + c4 * 2) = ph;
                    *reinterpret_cast<uint2*>(smem + (st * 2 + 1) * ABUF + row * 80 + c4 * 2) = pl;
                }
            }
            if (BF32) {
#pragma unroll
                for (int it = 0; it < 4; it++) {
                    int slot = tid + it * 256;
                    int row = slot >> 5, c4 = (slot & 31) * 4;
                    float4 v = *reinterpret_cast<const float4*>(smem + OFF_BF + st * BFSTG + row * 544 + c4 * 4);
                    uint2 ph, pl;
                    split4(v, ph, pl);
                    *reinterpret_cast<uint2*>(smem + OFF_B + (st * 2 + 0) * BBUF + row * 272 + c4 * 2) = ph;
                    *reinterpret_cast<uint2*>(smem + OFF_B + (st * 2 + 1) * BBUF + row * 272 + c4 * 2) = pl;
                }
            }
            __syncthreads();
        }

        const uint32_t aHiB = sb + (st * 2 + 0) * ABUF;
        const uint32_t aLoB = sb + (st * 2 + 1) * ABUF;
        const uint32_t bHiB = sb + OFF_B + (st * 2 + 0) * BBUF;
        const uint32_t bLoB = sb + OFF_B + (st * 2 + 1) * BBUF;
#pragma unroll
        for (int kk = 0; kk < 2; kk++) {
            uint32_t bh[8], bl[8], ah[4][4], al[4][4];
#pragma unroll
            for (int p = 0; p < 2; p++) {
                ldm_x4_t(&bh[p * 4], bHiB + bFrag + kk * 4352 + p * 32);
                ldm_x4_t(&bl[p * 4], bLoB + bFrag + kk * 4352 + p * 32);
            }
#pragma unroll
            for (int mt = 0; mt < 4; mt++) {
                ldm_x4(ah[mt], aHiB + aFrag + mt * 1280 + kk * 32);
                ldm_x4(al[mt], aLoB + aFrag + mt * 1280 + kk * 32);
            }
#pragma unroll
            for (int mt = 0; mt < 4; mt++) {
#pragma unroll
                for (int nt = 0; nt < 4; nt++) {
                    const uint32_t* bhp = &bh[(nt >> 1) * 4 + (nt & 1) * 2];
                    const uint32_t* blp = &bl[(nt >> 1) * 4 + (nt & 1) * 2];
                    mma16816(acc[mt][nt], ah[mt], bhp);
                    mma16816(acc[mt][nt], ah[mt], blp);
                    mma16816(acc[mt][nt], al[mt], bhp);
                }
            }
        }
        __syncthreads();
    }

#pragma unroll
    for (int mt = 0; mt < 4; mt++) {
#pragma unroll
        for (int nt = 0; nt < 4; nt++) {
            int row = m0 + mBase + mt * 16 + g;
            int col = n0 + nBase + nt * 8 + 2 * t;
            if (EPI == 0) {
                *reinterpret_cast<float2*>(out + (size_t)row * outLd + col) =
                    make_float2(acc[mt][nt][0], acc[mt][nt][1]);
                *reinterpret_cast<float2*>(out + (size_t)(row + 8) * outLd + col) =
                    make_float2(acc[mt][nt][2], acc[mt][nt][3]);
            } else if (EPI == 2) {
                float* p0 = out + (size_t)row * outLd + col;
                float* p1 = out + (size_t)(row + 8) * outLd + col;
                atomicAdd(p0,     acc[mt][nt][0]);
                atomicAdd(p0 + 1, acc[mt][nt][1]);
                atomicAdd(p1,     acc[mt][nt][2]);
                atomicAdd(p1 + 1, acc[mt][nt][3]);
            } else {  // EPI == 3
#pragma unroll
                for (int hh = 0; hh < 2; hh++) {
                    __nv_bfloat16 h0, l0, h1, l1;
                    split_bf16(acc[mt][nt][hh * 2 + 0], h0, l0);
                    split_bf16(acc[mt][nt][hh * 2 + 1], h1, l1);
                    size_t o = (size_t)(row + hh * 8) * outLd + col;
                    *reinterpret_cast<uint32_t*>(ohi + o) = pack2(h0, h1);
                    *reinterpret_cast<uint32_t*>(olo + o) = pack2(l0, l1);
                }
            }
        }
    }
}

// ---------------------------------------------------------------------------
// GEMM1 fused: Klog[j][o] = sum_c key[c][j]*Wk[o][c], then k-softmax over o,
// store Ks [j][o] bf16 hi/lo row-major.
// A = key fp32 TRANS source [c][j] (in-kernel split); B = Wk bf16 normal, BN=256.
// ---------------------------------------------------------------------------
static constexpr int KSM_BBUF  = 20480;                 // 256 x 80
static constexpr int KSM_OFF_A = 4 * KSM_BBUF;          // 81920
static constexpr int KSM_ABUF  = 8704;                  // 32 x 272 (trans bf16)
static constexpr int KSM_OFF_AF = KSM_OFF_A + 4 * KSM_ABUF;  // 116736
static constexpr int KSM_SMEM  = KSM_OFF_AF + 2 * BFSTG;     // 151552

__global__ void __launch_bounds__(256, 1) gemm_ksm_kernel(
    const float* __restrict__ keyP,          // key + S0_, ld = S_
    const __nv_bfloat16* __restrict__ Bh, const __nv_bfloat16* __restrict__ Bl,
    __nv_bfloat16* __restrict__ Ks_hi, __nv_bfloat16* __restrict__ Ks_lo)
{
    extern __shared__ char smem[];
    uint32_t sb = smem_u32(smem);
    const int tid  = threadIdx.x;
    const int wid  = tid >> 5;
    const int lane = tid & 31;
    const int j0 = blockIdx.x * 128;

    const int wm = wid >> 2, wn = wid & 3;
    const int mBase = wm * 64, nBase = wn * 64;
    const int g = lane >> 2, t = lane & 3;
    const int mat = lane >> 3, r = lane & 7;

    // A trans fragment: row = (mat>>1)*8 + r (k), col = mBase + (mat&1)*8 (m)
    const uint32_t aFragT = (uint32_t)((mat >> 1) * 8 + r) * 272 + (mBase + (mat & 1) * 8) * 2;
    // B normal fragment (256-row tile)
    const uint32_t bFrag = (uint32_t)(nBase + (mat >> 1) * 8 + r) * 80 + (mat & 1) * 16;

    float acc[4][8][4];
#pragma unroll
    for (int i = 0; i < 4; i++)
#pragma unroll
        for (int j = 0; j < 8; j++)
#pragma unroll
            for (int e = 0; e < 4; e++) acc[i][j][e] = 0.0f;

    auto load_stage = [&](int st, int kOff) {
#pragma unroll
        for (int i = 0; i < 12; i++) {
            int idx = tid + i * 256;   // 0..3071
            if (idx < 1024) {          // A fp32 trans: 32 rows x 512B
                int row = idx >> 5, ch = idx & 31;
                cp16(sb + KSM_OFF_AF + st * BFSTG + row * 544 + ch * 16,
                     keyP + (size_t)(kOff + row) * S_ + j0 + ch * 4);
            } else {                   // B bf16 normal: 256 rows x 64B x2
                int idx2 = idx - 1024;
                int hl = idx2 >> 10, rem = idx2 & 1023;
                int row = rem >> 2, ch = rem & 3;
                cp16(sb + (st * 2 + hl) * KSM_BBUF + row * 80 + ch * 16,
                     (hl ? Bl : Bh) + (size_t)row * C_ + kOff + ch * 8);
            }
        }
    };

    load_stage(0, 0);
    cp_commit();

    const int nChunks = 8;   // K = 256
    for (int ch = 0; ch < nChunks; ch++) {
        if (ch + 1 < nChunks) {
            load_stage((ch + 1) & 1, (ch + 1) * 32);
            cp_commit();
            cp_wait<1>();
        } else {
            cp_wait<0>();
        }
        __syncthreads();

        const int st = ch & 1;
        // convert A fp32 stage -> bf16 trans buffers
#pragma unroll
        for (int it = 0; it < 4; it++) {
            int slot = tid + it * 256;
            int row = slot >> 5, c4 = (slot & 31) * 4;
            float4 v = *reinterpret_cast<const float4*>(smem + KSM_OFF_AF + st * BFSTG + row * 544 + c4 * 4);
            uint2 ph, pl;
            split4(v, ph, pl);
            *reinterpret_cast<uint2*>(smem + KSM_OFF_A + (st * 2 + 0) * KSM_ABUF + row * 272 + c4 * 2) = ph;
            *reinterpret_cast<uint2*>(smem + KSM_OFF_A + (st * 2 + 1) * KSM_ABUF + row * 272 + c4 * 2) = pl;
        }
        __syncthreads();

        const uint32_t aHiB = sb + KSM_OFF_A + (st * 2 + 0) * KSM_ABUF;
        const uint32_t aLoB = sb + KSM_OFF_A + (st * 2 + 1) * KSM_ABUF;
        const uint32_t bHiB = sb + (st * 2 + 0) * KSM_BBUF;
        const uint32_t bLoB = sb + (st * 2 + 1) * KSM_BBUF;
#pragma unroll
        for (int kk = 0; kk < 2; kk++) {
            uint32_t ah[4][4], al[4][4];
#pragma unroll
            for (int mt = 0; mt < 4; mt++) {
                ldm_x4_t(ah[mt], aHiB + aFragT + kk * 4352 + mt * 32);
                ldm_x4_t(al[mt], aLoB + aFragT + kk * 4352 + mt * 32);
            }
#pragma unroll
            for (int ph = 0; ph < 2; ph++) {
                uint32_t bh8[8], bl8[8];
#pragma unroll
                for (int pl = 0; pl < 2; pl++) {
                    ldm_x4(&bh8[pl * 4], bHiB + bFrag + (ph * 2 + pl) * 1280 + kk * 32);
                    ldm_x4(&bl8[pl * 4], bLoB + bFrag + (ph * 2 + pl) * 1280 + kk * 32);
                }
#pragma unroll
                for (int mt = 0; mt < 4; mt++) {
#pragma unroll
                    for (int l = 0; l < 4; l++) {
                        const uint32_t* bhp = &bh8[(l >> 1) * 4 + (l & 1) * 2];
                        const uint32_t* blp = &bl8[(l >> 1) * 4 + (l & 1) * 2];
                        int nt = ph * 4 + l;
                        mma16816(acc[mt][nt], ah[mt], bhp);
                        mma16816(acc[mt][nt], ah[mt], blp);
                        mma16816(acc[mt][nt], al[mt], bhp);
                    }
                }
            }
        }
        __syncthreads();
    }

    // ---------------- fused epilogue: row softmax over 256 cols ------------
    float* redA = reinterpret_cast<float*>(smem);
    float* redB = redA + 512;

    float rmax[4][2];
#pragma unroll
    for (int mt = 0; mt < 4; mt++) {
#pragma unroll
        for (int h = 0; h < 2; h++) {
            float m = -1e30f;
#pragma unroll
            for (int nt = 0; nt < 8; nt++) {
                m = fmaxf(m, acc[mt][nt][h * 2 + 0]);
                m = fmaxf(m, acc[mt][nt][h * 2 + 1]);
            }
            m = fmaxf(m, __shfl_xor_sync(0xffffffffu, m, 1));
            m = fmaxf(m, __shfl_xor_sync(0xffffffffu, m, 2));
            if (t == 0) redA[(mBase + mt * 16 + h * 8 + g) * 4 + wn] = m;
        }
    }
    __syncthreads();
#pragma unroll
    for (int mt = 0; mt < 4; mt++)
#pragma unroll
        for (int h = 0; h < 2; h++) {
            int row = mBase + mt * 16 + h * 8 + g;
            float m = fmaxf(fmaxf(redA[row * 4], redA[row * 4 + 1]),
                            fmaxf(redA[row * 4 + 2], redA[row * 4 + 3]));
            rmax[mt][h] = m * INV_TEMP;
        }

    float rinv[4][2];
#pragma unroll
    for (int mt = 0; mt < 4; mt++) {
#pragma unroll
        for (int h = 0; h < 2; h++) {
            float s = 0.0f;
#pragma unroll
            for (int nt = 0; nt < 8; nt++) {
#pragma unroll
                for (int e2 = 0; e2 < 2; e2++) {
                    float w = __expf(acc[mt][nt][h * 2 + e2] * INV_TEMP - rmax[mt][h]);
                    acc[mt][nt][h * 2 + e2] = w;
                    s += w;
                }
            }
            s += __shfl_xor_sync(0xffffffffu, s, 1);
            s += __shfl_xor_sync(0xffffffffu, s, 2);
            if (t == 0) redB[(mBase + mt * 16 + h * 8 + g) * 4 + wn] = s;
        }
    }
    __syncthreads();
#pragma unroll
    for (int mt = 0; mt < 4; mt++)
#pragma unroll
        for (int h = 0; h < 2; h++) {
            int row = mBase + mt * 16 + h * 8 + g;
            float s = redB[row * 4] + redB[row * 4 + 1] + redB[row * 4 + 2] + redB[row * 4 + 3];
            rinv[mt][h] = 1.0f / s;
        }

    // row-major store Ks [j][o]
#pragma unroll
    for (int mt = 0; mt < 4; mt++) {
#pragma unroll
        for (int h = 0; h < 2; h++) {
            int j = j0 + mBase + mt * 16 + h * 8 + g;
#pragma unroll
            for (int nt = 0; nt < 8; nt++) {
                int col = nBase + nt * 8 + 2 * t;
                float w0 = acc[mt][nt][h * 2 + 0] * rinv[mt][h];
                float w1 = acc[mt][nt][h * 2 + 1] * rinv[mt][h];
                __nv_bfloat16 h0, l0, h1, l1;
                split_bf16(w0, h0, l0);
                split_bf16(w1, h1, l1);
                size_t o = (size_t)j * C_ + col;
                *reinterpret_cast<uint32_t*>(Ks_hi + o) = pack2(h0, h1);
                *reinterpret_cast<uint32_t*>(Ks_lo + o) = pack2(l0, l1);
            }
        }
    }
}

// ---------------------------------------------------------------------------
// q softmax over hw (rows of 4096): fp32 in -> bf16 hi/lo out (same layout)
// ---------------------------------------------------------------------------
__global__ void __launch_bounds__(256) qsoftmax_kernel(
    const float* __restrict__ Qlog,
    __nv_bfloat16* __restrict__ Qs_hi, __nv_bfloat16* __restrict__ Qs_lo)
{
    constexpr int NT = 256, NE = 16;
    const float* row = Qlog + (size_t)blockIdx.x * HW_;
    __shared__ float sred[32];
    const int tid = threadIdx.x;
    const int lane = tid & 31;
    const int wid = tid >> 5;

    float v[NE];
    float m = -1e30f;
#pragma unroll
    for (int e = 0; e < NE; e++) {
        v[e] = row[tid + e * NT] * INV_TEMP;
        m = fmaxf(m, v[e]);
    }
#pragma unroll
    for (int o = 16; o > 0; o >>= 1) m = fmaxf(m, __shfl_xor_sync(0xffffffffu, m, o));
    if (lane == 0) sred[wid] = m;
    __syncthreads();
    if (wid == 0) {
        float tv = (lane < 8) ? sred[lane] : -1e30f;
#pragma unroll
        for (int o = 16; o > 0; o >>= 1) tv = fmaxf(tv, __shfl_xor_sync(0xffffffffu, tv, o));
        if (lane == 0) sred[0] = tv;
    }
    __syncthreads();
    m = sred[0];
    __syncthreads();

    float sum = 0.0f;
#pragma unroll
    for (int e = 0; e < NE; e++) {
        v[e] = __expf(v[e] - m);
        sum += v[e];
    }
#pragma unroll
    for (int o = 16; o > 0; o >>= 1) sum += __shfl_xor_sync(0xffffffffu, sum, o);
    if (lane == 0) sred[wid] = sum;
    __syncthreads();
    if (wid == 0) {
        float tv = (lane < 8) ? sred[lane] : 0.0f;
#pragma unroll
        for (int o = 16; o > 0; o >>= 1) tv += __shfl_xor_sync(0xffffffffu, tv, o);
        if (lane == 0) sred[0] = tv;
    }
    __syncthreads();
    float inv = 1.0f / sred[0];
    size_t base = (size_t)blockIdx.x * HW_;
#pragma unroll
    for (int e = 0; e < NE; e++) {
        float w = v[e] * inv;
        __nv_bfloat16 h, l;
        split_bf16(w, h, l);
        Qs_hi[base + tid + e * NT] = h;
        Qs_lo[base + tid + e * NT] = l;
    }
}

__global__ void zero_kernel(float* __restrict__ p, int n)
{
    int i = blockIdx.x * blockDim.x + threadIdx.x;
    if (i < n) p[i] = 0.0f;
}

// ---------------------------------------------------------------------------
// Launch
// ---------------------------------------------------------------------------
extern "C" void kernel_launch(void* const* d_in, const int* in_sizes, int n_in,
                              void* d_out, int out_size)
{
    (void)in_sizes; (void)n_in; (void)out_size;
    const float* query = (const float*)d_in[0]; // (C, HW)
    const float* key   = (const float*)d_in[1]; // (C, S)
    const float* value = (const float*)d_in[2]; // (C, S)
    const float* Wq    = (const float*)d_in[3]; // (C, C)
    const float* Wk    = (const float*)d_in[4];
    const float* Wv    = (const float*)d_in[5];
    float* out = (float*)d_out;                 // (C, HW)

    cudaFuncSetAttribute(gemm_uni_kernel<0, false, true>,  cudaFuncAttributeMaxDynamicSharedMemorySize, GEMM_SMEM);
    cudaFuncSetAttribute(gemm_uni_kernel<2, true,  false>, cudaFuncAttributeMaxDynamicSharedMemorySize, GEMM_SMEM);
    cudaFuncSetAttribute(gemm_uni_kernel<3, false, true>,  cudaFuncAttributeMaxDynamicSharedMemorySize, GEMM_SMEM);
    cudaFuncSetAttribute(gemm_uni_kernel<0, false, false>, cudaFuncAttributeMaxDynamicSharedMemorySize, GEMM_SMEM);
    cudaFuncSetAttribute(gemm_ksm_kernel, cudaFuncAttributeMaxDynamicSharedMemorySize, KSM_SMEM);

    __nv_bfloat16 *Ks_hi, *Ks_lo, *Qs_hi, *Qs_lo;
    __nv_bfloat16 *Wq_hi, *Wq_lo, *Wk_hi, *Wk_lo, *Wv_hi, *Wv_lo, *G_hi, *G_lo;
    float *Qlog, *T2;
    cudaGetSymbolAddress((void**)&Ks_hi, g_Ks_hi);
    cudaGetSymbolAddress((void**)&Ks_lo, g_Ks_lo);
    cudaGetSymbolAddress((void**)&Qs_hi, g_Qs_hi);
    cudaGetSymbolAddress((void**)&Qs_lo, g_Qs_lo);
    cudaGetSymbolAddress((void**)&Wq_hi, g_Wq_hi);
    cudaGetSymbolAddress((void**)&Wq_lo, g_Wq_lo);
    cudaGetSymbolAddress((void**)&Wk_hi, g_Wk_hi);
    cudaGetSymbolAddress((void**)&Wk_lo, g_Wk_lo);
    cudaGetSymbolAddress((void**)&Wv_hi, g_Wv_hi);
    cudaGetSymbolAddress((void**)&Wv_lo, g_Wv_lo);
    cudaGetSymbolAddress((void**)&G_hi,  g_G_hi);
    cudaGetSymbolAddress((void**)&G_lo,  g_G_lo);
    cudaGetSymbolAddress((void**)&Qlog,  g_Qlog);
    cudaGetSymbolAddress((void**)&T2,    g_T2);

    // 1) weights fp32 -> bf16 hi/lo
    convW3_kernel<<<dim3(64, 1, 3), 256>>>(Wq, Wk, Wv, Wq_hi, Wq_lo, Wk_hi, Wk_lo, Wv_hi, Wv_lo);

    // 2) GEMM1 + fused k-softmax: key (fp32, trans, in-kernel split) x Wk -> Ks [j][o]
    gemm_ksm_kernel<<<SA_ / 128, 256, KSM_SMEM>>>(key + S0_, Wk_hi, Wk_lo, Ks_hi, Ks_lo);

    // 3) GEMM2: Qlog[o][hw] = Wq . query (query fp32 trans, in-kernel split)
    gemm_uni_kernel<0, false, true><<<dim3(HW_ / 128, C_ / 128, 1), 256, GEMM_SMEM>>>(
        Wq_hi, Wq_lo, nullptr, C_, nullptr, nullptr, query, HW_,
        Qlog, HW_, C_, nullptr, nullptr);

    // 4) q softmax -> Qs bf16 hi/lo [o][hw]
    qsoftmax_kernel<<<C_, 256>>>(Qlog, Qs_hi, Qs_lo);

    // 5) T2[a][o] = sum_j value[a][j] * Ks[j][o]   (value fp32 normal, split-K 32)
    zero_kernel<<<(C_ * C_ + 255) / 256, 256>>>(T2, C_ * C_);
    gemm_uni_kernel<2, true, false><<<dim3(C_ / 128, C_ / 128, 32), 256, GEMM_SMEM>>>(
        nullptr, nullptr, value + S0_, S_, Ks_hi, Ks_lo, nullptr, C_,
        T2, C_, SA_ / 32, nullptr, nullptr);

    // 6) G[c][o] = sum_a Wv[c][a] * T2[a][o]   (T2 fp32 trans) -> bf16 hi/lo
    gemm_uni_kernel<3, false, true><<<dim3(C_ / 128, C_ / 128, 1), 256, GEMM_SMEM>>>(
        Wv_hi, Wv_lo, nullptr, C_, nullptr, nullptr, T2, C_,
        nullptr, C_, C_, G_hi, G_lo);

    // 7) out[c][hw] = sum_o G[c][o] * Qs[o][hw]
    gemm_uni_kernel<0, false, false><<<dim3(HW_ / 128, C_ / 128, 1), 256, GEMM_SMEM>>>(
        G_hi, G_lo, nullptr, C_, Qs_hi, Qs_lo, nullptr, HW_,
        out, HW_, C_, nullptr, nullptr);
}

// round 6
// speedup vs baseline: 1.2639x; 1.1759x over previous
#include <cuda_runtime.h>
#include <cuda_bf16.h>
#include <cstdint>

// ---------------------------------------------------------------------------
// Problem constants (B=1)
// ---------------------------------------------------------------------------
static constexpr int C_   = 256;
static constexpr int HW_  = 4096;     // 64*64
static constexpr int S_   = 32768;    // 8*64*64
static constexpr int SA_  = 20480;    // 5*64*64 active (last 5 frames)
static constexpr int S0_  = S_ - SA_; // 12288
static constexpr float INV_TEMP = 10.0f;

// ---------------------------------------------------------------------------
// Device scratch
// ---------------------------------------------------------------------------
__device__ __align__(16) __nv_bfloat16 g_Ks_hi [SA_ * C_];   // [j][o]  (k-softmaxed)
__device__ __align__(16) __nv_bfloat16 g_Ks_lo [SA_ * C_];
__device__ __align__(16) __nv_bfloat16 g_Qs_hi [C_ * HW_];   // [o][hw] (q-softmaxed)
__device__ __align__(16) __nv_bfloat16 g_Qs_lo [C_ * HW_];
__device__ __align__(16) __nv_bfloat16 g_Wq_hi[C_ * C_], g_Wq_lo[C_ * C_];
__device__ __align__(16) __nv_bfloat16 g_Wk_hi[C_ * C_], g_Wk_lo[C_ * C_];
__device__ __align__(16) __nv_bfloat16 g_Wv_hi[C_ * C_], g_Wv_lo[C_ * C_];
__device__ __align__(16) __nv_bfloat16 g_G_hi [C_ * C_], g_G_lo [C_ * C_];
__device__ __align__(16) float g_Qlog[C_ * HW_];   // q logits (split-K accumulator)
__device__ __align__(16) float g_T2  [C_ * C_];    // split-K accumulator [a][o]

// ---------------------------------------------------------------------------
// PTX helpers (compute_100-safe)
// ---------------------------------------------------------------------------
__device__ __forceinline__ uint32_t smem_u32(const void* p) {
    uint32_t a;
    asm("{ .reg .u64 t; cvta.to.shared.u64 t, %1; cvt.u32.u64 %0, t; }" : "=r"(a) : "l"(p));
    return a;
}
__device__ __forceinline__ void cp16(uint32_t dst, const void* src) {
    asm volatile("cp.async.cg.shared.global [%0], [%1], 16;" :: "r"(dst), "l"(src));
}
__device__ __forceinline__ void cp_commit() {
    asm volatile("cp.async.commit_group;" ::: "memory");
}
template<int N>
__device__ __forceinline__ void cp_wait() {
    asm volatile("cp.async.wait_group %0;" :: "n"(N) : "memory");
}
__device__ __forceinline__ void ldm_x4(uint32_t* r, uint32_t addr) {
    asm volatile("ldmatrix.sync.aligned.m8n8.x4.shared.b16 {%0,%1,%2,%3}, [%4];"
                 : "=r"(r[0]), "=r"(r[1]), "=r"(r[2]), "=r"(r[3]) : "r"(addr));
}
__device__ __forceinline__ void ldm_x4_t(uint32_t* r, uint32_t addr) {
    asm volatile("ldmatrix.sync.aligned.m8n8.x4.trans.shared.b16 {%0,%1,%2,%3}, [%4];"
                 : "=r"(r[0]), "=r"(r[1]), "=r"(r[2]), "=r"(r[3]) : "r"(addr));
}
__device__ __forceinline__ void mma16816(float* c, const uint32_t* a, const uint32_t* b) {
    asm volatile(
        "mma.sync.aligned.m16n8k16.row.col.f32.bf16.bf16.f32 "
        "{%0,%1,%2,%3}, {%4,%5,%6,%7}, {%8,%9}, {%0,%1,%2,%3};"
        : "+f"(c[0]), "+f"(c[1]), "+f"(c[2]), "+f"(c[3])
        : "r"(a[0]), "r"(a[1]), "r"(a[2]), "r"(a[3]), "r"(b[0]), "r"(b[1]));
}
__device__ __forceinline__ void split_bf16(float v, __nv_bfloat16& h, __nv_bfloat16& l) {
    h = __float2bfloat16(v);
    l = __float2bfloat16(v - __bfloat162float(h));
}
__device__ __forceinline__ uint32_t pack2(__nv_bfloat16 a, __nv_bfloat16 b) {
    return (uint32_t)__bfloat16_as_ushort(a) | ((uint32_t)__bfloat16_as_ushort(b) << 16);
}
__device__ __forceinline__ void split4(float4 v, uint2& ph, uint2& pl) {
    __nv_bfloat16 h0, l0, h1, l1, h2, l2, h3, l3;
    split_bf16(v.x, h0, l0); split_bf16(v.y, h1, l1);
    split_bf16(v.z, h2, l2); split_bf16(v.w, h3, l3);
    ph = make_uint2(pack2(h0, h1), pack2(h2, h3));
    pl = make_uint2(pack2(l0, l1), pack2(l2, l3));
}

// ---------------------------------------------------------------------------
// 3 weight matrices (256x256) fp32 -> bf16 hi/lo, one launch via grid.z
// ---------------------------------------------------------------------------
__global__ void convW3_kernel(const float* __restrict__ s0, const float* __restrict__ s1,
                              const float* __restrict__ s2,
                              __nv_bfloat16* __restrict__ h0, __nv_bfloat16* __restrict__ l0,
                              __nv_bfloat16* __restrict__ h1, __nv_bfloat16* __restrict__ l1,
                              __nv_bfloat16* __restrict__ h2, __nv_bfloat16* __restrict__ l2)
{
    const float* src = (blockIdx.z == 0) ? s0 : (blockIdx.z == 1) ? s1 : s2;
    __nv_bfloat16* hi = (blockIdx.z == 0) ? h0 : (blockIdx.z == 1) ? h1 : h2;
    __nv_bfloat16* lo = (blockIdx.z == 0) ? l0 : (blockIdx.z == 1) ? l1 : l2;
    int idx = blockIdx.x * blockDim.x + threadIdx.x;   // 16384 float4 slots
    float4 v = *reinterpret_cast<const float4*>(src + idx * 4);
    uint2 ph, pl;
    split4(v, ph, pl);
    *reinterpret_cast<uint2*>(hi + idx * 4) = ph;
    *reinterpret_cast<uint2*>(lo + idx * 4) = pl;
}

// ---------------------------------------------------------------------------
// Generic tensor-core GEMM:  D[m,n] (+)= sum_k A[m,k]*B[n,k], bf16x3 split.
// A: normal layout (K-major rows m), bf16 pair OR fp32 (in-kernel split).
// B: TRANS source layout [k][n] (row-major global), bf16 pair OR fp32.
// BM=BN=128, BK=32, 256 threads, 2-stage cp.async.
// EPI: 0 fp32 store | 2 fp32 atomicAdd | 3 bf16 hi/lo split store
// ---------------------------------------------------------------------------
static constexpr int ABUF = 10240;   // 128 x 80
static constexpr int BBUF = 8704;    // 32 x 272
static constexpr int OFF_B  = 4 * ABUF;            // 40960
static constexpr int OFF_AF = OFF_B + 4 * BBUF;    // 75776
static constexpr int AFSTG  = 18432;               // 128 x 144
static constexpr int BFSTG  = 17408;               // 32 x 544
static constexpr int GEMM_SMEM = OFF_AF + 2 * AFSTG + 2 * BFSTG;

template<int EPI, bool AF32, bool BF32>
__global__ void __launch_bounds__(256, 1) gemm_uni_kernel(
    const __nv_bfloat16* __restrict__ Ah, const __nv_bfloat16* __restrict__ Al,
    const float* __restrict__ Af, int aLd,
    const __nv_bfloat16* __restrict__ Bh, const __nv_bfloat16* __restrict__ Bl,
    const float* __restrict__ Bf, int bLd,
    float* __restrict__ out, int outLd, int kPerCta,
    __nv_bfloat16* __restrict__ ohi, __nv_bfloat16* __restrict__ olo)
{
    extern __shared__ char smem[];
    uint32_t sb = smem_u32(smem);
    const int tid  = threadIdx.x;
    const int wid  = tid >> 5;
    const int lane = tid & 31;
    const int m0 = blockIdx.y * 128;
    const int n0 = blockIdx.x * 128;
    const int kStart = blockIdx.z * kPerCta;
    const int nChunks = kPerCta >> 5;

    const uint32_t OFF_BF = OFF_AF + (AF32 ? 2 * AFSTG : 0);

    const int wm = wid >> 2, wn = wid & 3;
    const int mBase = wm * 64, nBase = wn * 32;
    const int g = lane >> 2, t = lane & 3;
    const int mat = lane >> 3, r = lane & 7;

    const uint32_t aFrag = (uint32_t)(mBase + (mat & 1) * 8 + r) * 80 + (mat >> 1) * 16;
    const uint32_t bFrag = (uint32_t)((mat & 1) * 8 + r) * 272 + (nBase + (mat >> 1) * 8) * 2;

    float acc[4][4][4];
#pragma unroll
    for (int i = 0; i < 4; i++)
#pragma unroll
        for (int j = 0; j < 4; j++)
#pragma unroll
            for (int e = 0; e < 4; e++) acc[i][j][e] = 0.0f;

    auto load_stage = [&](int st, int kOff) {
#pragma unroll
        for (int i = 0; i < 8; i++) {
            int idx = tid + i * 256;
            if (idx < 1024) {
                if (AF32) {
                    int row = idx >> 3, ch = idx & 7;
                    cp16(sb + OFF_AF + st * AFSTG + row * 144 + ch * 16,
                         Af + (size_t)(m0 + row) * aLd + kOff + ch * 4);
                } else {
                    int hl = idx >> 9, rem = idx & 511;
                    int row = rem >> 2, ch = rem & 3;
                    cp16(sb + (st * 2 + hl) * ABUF + row * 80 + ch * 16,
                         (hl ? Al : Ah) + (size_t)(m0 + row) * aLd + kOff + ch * 8);
                }
            } else {
                int idx2 = idx - 1024;
                if (BF32) {
                    int row = idx2 >> 5, ch = idx2 & 31;
                    cp16(sb + OFF_BF + st * BFSTG + row * 544 + ch * 16,
                         Bf + (size_t)(kOff + row) * bLd + n0 + ch * 4);
                } else {
                    int hl = idx2 >> 9, rem = idx2 & 511;
                    int row = rem >> 4, ch = rem & 15;
                    cp16(sb + OFF_B + (st * 2 + hl) * BBUF + row * 272 + ch * 16,
                         (hl ? Bl : Bh) + (size_t)(kOff + row) * bLd + n0 + ch * 8);
                }
            }
        }
    };

    load_stage(0, kStart);
    cp_commit();

    for (int ch = 0; ch < nChunks; ch++) {
        if (ch + 1 < nChunks) {
            load_stage((ch + 1) & 1, kStart + (ch + 1) * 32);
            cp_commit();
            cp_wait<1>();
        } else {
            cp_wait<0>();
        }
        __syncthreads();

        const int st = ch & 1;
        if (AF32 || BF32) {
            if (AF32) {
#pragma unroll
                for (int it = 0; it < 4; it++) {
                    int slot = tid + it * 256;
                    int row = slot >> 3, c4 = (slot & 7) * 4;
                    float4 v = *reinterpret_cast<const float4*>(smem + OFF_AF + st * AFSTG + row * 144 + c4 * 4);
                    uint2 ph, pl;
                    split4(v, ph, pl);
                    *reinterpret_cast<uint2*>(smem + (st * 2 + 0) * ABUF + row * 80 + c4 * 2) = ph;
                    *reinterpret_cast<uint2*>(smem + (st * 2 + 1) * ABUF + row * 80 + c4 * 2) = pl;
                }
            }
            if (BF32) {
#pragma unroll
                for (int it = 0; it < 4; it++) {
                    int slot = tid + it * 256;
                    int row = slot >> 5, c4 = (slot & 31) * 4;
                    float4 v = *reinterpret_cast<const float4*>(smem + OFF_BF + st * BFSTG + row * 544 + c4 * 4);
                    uint2 ph, pl;
                    split4(v, ph, pl);
                    *reinterpret_cast<uint2*>(smem + OFF_B + (st * 2 + 0) * BBUF + row * 272 + c4 * 2) = ph;
                    *reinterpret_cast<uint2*>(smem + OFF_B + (st * 2 + 1) * BBUF + row * 272 + c4 * 2) = pl;
                }
            }
            __syncthreads();
        }

        const uint32_t aHiB = sb + (st * 2 + 0) * ABUF;
        const uint32_t aLoB = sb + (st * 2 + 1) * ABUF;
        const uint32_t bHiB = sb + OFF_B + (st * 2 + 0) * BBUF;
        const uint32_t bLoB = sb + OFF_B + (st * 2 + 1) * BBUF;
#pragma unroll
        for (int kk = 0; kk < 2; kk++) {
            uint32_t bh[8], bl[8], ah[4][4], al[4][4];
#pragma unroll
            for (int p = 0; p < 2; p++) {
                ldm_x4_t(&bh[p * 4], bHiB + bFrag + kk * 4352 + p * 32);
                ldm_x4_t(&bl[p * 4], bLoB + bFrag + kk * 4352 + p * 32);
            }
#pragma unroll
            for (int mt = 0; mt < 4; mt++) {
                ldm_x4(ah[mt], aHiB + aFrag + mt * 1280 + kk * 32);
                ldm_x4(al[mt], aLoB + aFrag + mt * 1280 + kk * 32);
            }
#pragma unroll
            for (int mt = 0; mt < 4; mt++) {
#pragma unroll
                for (int nt = 0; nt < 4; nt++) {
                    const uint32_t* bhp = &bh[(nt >> 1) * 4 + (nt & 1) * 2];
                    const uint32_t* blp = &bl[(nt >> 1) * 4 + (nt & 1) * 2];
                    mma16816(acc[mt][nt], ah[mt], bhp);
                    mma16816(acc[mt][nt], ah[mt], blp);
                    mma16816(acc[mt][nt], al[mt], bhp);
                }
            }
        }
        __syncthreads();
    }

#pragma unroll
    for (int mt = 0; mt < 4; mt++) {
#pragma unroll
        for (int nt = 0; nt < 4; nt++) {
            int row = m0 + mBase + mt * 16 + g;
            int col = n0 + nBase + nt * 8 + 2 * t;
            if (EPI == 0) {
                *reinterpret_cast<float2*>(out + (size_t)row * outLd + col) =
                    make_float2(acc[mt][nt][0], acc[mt][nt][1]);
                *reinterpret_cast<float2*>(out + (size_t)(row + 8) * outLd + col) =
                    make_float2(acc[mt][nt][2], acc[mt][nt][3]);
            } else if (EPI == 2) {
                float* p0 = out + (size_t)row * outLd + col;
                float* p1 = out + (size_t)(row + 8) * outLd + col;
                atomicAdd(p0,     acc[mt][nt][0]);
                atomicAdd(p0 + 1, acc[mt][nt][1]);
                atomicAdd(p1,     acc[mt][nt][2]);
                atomicAdd(p1 + 1, acc[mt][nt][3]);
            } else {  // EPI == 3
#pragma unroll
                for (int hh = 0; hh < 2; hh++) {
                    __nv_bfloat16 h0, l0, h1, l1;
                    split_bf16(acc[mt][nt][hh * 2 + 0], h0, l0);
                    split_bf16(acc[mt][nt][hh * 2 + 1], h1, l1);
                    size_t o = (size_t)(row + hh * 8) * outLd + col;
                    *reinterpret_cast<uint32_t*>(ohi + o) = pack2(h0, h1);
                    *reinterpret_cast<uint32_t*>(olo + o) = pack2(l0, l1);
                }
            }
        }
    }
}

// ---------------------------------------------------------------------------
// GEMM1 fused: Klog[j][o] = sum_c key[c][j]*Wk[o][c], then k-softmax over o,
// store Ks [j][o] bf16 hi/lo row-major.
// ---------------------------------------------------------------------------
static constexpr int KSM_BBUF  = 20480;                 // 256 x 80
static constexpr int KSM_OFF_A = 4 * KSM_BBUF;          // 81920
static constexpr int KSM_ABUF  = 8704;                  // 32 x 272 (trans bf16)
static constexpr int KSM_OFF_AF = KSM_OFF_A + 4 * KSM_ABUF;  // 116736
static constexpr int KSM_SMEM  = KSM_OFF_AF + 2 * BFSTG;     // 151552

__global__ void __launch_bounds__(256, 1) gemm_ksm_kernel(
    const float* __restrict__ keyP,          // key + S0_, ld = S_
    const __nv_bfloat16* __restrict__ Bh, const __nv_bfloat16* __restrict__ Bl,
    __nv_bfloat16* __restrict__ Ks_hi, __nv_bfloat16* __restrict__ Ks_lo)
{
    extern __shared__ char smem[];
    uint32_t sb = smem_u32(smem);
    const int tid  = threadIdx.x;
    const int wid  = tid >> 5;
    const int lane = tid & 31;
    const int j0 = blockIdx.x * 128;

    const int wm = wid >> 2, wn = wid & 3;
    const int mBase = wm * 64, nBase = wn * 64;
    const int g = lane >> 2, t = lane & 3;
    const int mat = lane >> 3, r = lane & 7;

    const uint32_t aFragT = (uint32_t)((mat >> 1) * 8 + r) * 272 + (mBase + (mat & 1) * 8) * 2;
    const uint32_t bFrag = (uint32_t)(nBase + (mat >> 1) * 8 + r) * 80 + (mat & 1) * 16;

    float acc[4][8][4];
#pragma unroll
    for (int i = 0; i < 4; i++)
#pragma unroll
        for (int j = 0; j < 8; j++)
#pragma unroll
            for (int e = 0; e < 4; e++) acc[i][j][e] = 0.0f;

    auto load_stage = [&](int st, int kOff) {
#pragma unroll
        for (int i = 0; i < 12; i++) {
            int idx = tid + i * 256;
            if (idx < 1024) {
                int row = idx >> 5, ch = idx & 31;
                cp16(sb + KSM_OFF_AF + st * BFSTG + row * 544 + ch * 16,
                     keyP + (size_t)(kOff + row) * S_ + j0 + ch * 4);
            } else {
                int idx2 = idx - 1024;
                int hl = idx2 >> 10, rem = idx2 & 1023;
                int row = rem >> 2, ch = rem & 3;
                cp16(sb + (st * 2 + hl) * KSM_BBUF + row * 80 + ch * 16,
                     (hl ? Bl : Bh) + (size_t)row * C_ + kOff + ch * 8);
            }
        }
    };

    load_stage(0, 0);
    cp_commit();

    const int nChunks = 8;
    for (int ch = 0; ch < nChunks; ch++) {
        if (ch + 1 < nChunks) {
            load_stage((ch + 1) & 1, (ch + 1) * 32);
            cp_commit();
            cp_wait<1>();
        } else {
            cp_wait<0>();
        }
        __syncthreads();

        const int st = ch & 1;
#pragma unroll
        for (int it = 0; it < 4; it++) {
            int slot = tid + it * 256;
            int row = slot >> 5, c4 = (slot & 31) * 4;
            float4 v = *reinterpret_cast<const float4*>(smem + KSM_OFF_AF + st * BFSTG + row * 544 + c4 * 4);
            uint2 ph, pl;
            split4(v, ph, pl);
            *reinterpret_cast<uint2*>(smem + KSM_OFF_A + (st * 2 + 0) * KSM_ABUF + row * 272 + c4 * 2) = ph;
            *reinterpret_cast<uint2*>(smem + KSM_OFF_A + (st * 2 + 1) * KSM_ABUF + row * 272 + c4 * 2) = pl;
        }
        __syncthreads();

        const uint32_t aHiB = sb + KSM_OFF_A + (st * 2 + 0) * KSM_ABUF;
        const uint32_t aLoB = sb + KSM_OFF_A + (st * 2 + 1) * KSM_ABUF;
        const uint32_t bHiB = sb + (st * 2 + 0) * KSM_BBUF;
        const uint32_t bLoB = sb + (st * 2 + 1) * KSM_BBUF;
#pragma unroll
        for (int kk = 0; kk < 2; kk++) {
            uint32_t ah[4][4], al[4][4];
#pragma unroll
            for (int mt = 0; mt < 4; mt++) {
                ldm_x4_t(ah[mt], aHiB + aFragT + kk * 4352 + mt * 32);
                ldm_x4_t(al[mt], aLoB + aFragT + kk * 4352 + mt * 32);
            }
#pragma unroll
            for (int ph = 0; ph < 2; ph++) {
                uint32_t bh8[8], bl8[8];
#pragma unroll
                for (int pl = 0; pl < 2; pl++) {
                    ldm_x4(&bh8[pl * 4], bHiB + bFrag + (ph * 2 + pl) * 1280 + kk * 32);
                    ldm_x4(&bl8[pl * 4], bLoB + bFrag + (ph * 2 + pl) * 1280 + kk * 32);
                }
#pragma unroll
                for (int mt = 0; mt < 4; mt++) {
#pragma unroll
                    for (int l = 0; l < 4; l++) {
                        const uint32_t* bhp = &bh8[(l >> 1) * 4 + (l & 1) * 2];
                        const uint32_t* blp = &bl8[(l >> 1) * 4 + (l & 1) * 2];
                        int nt = ph * 4 + l;
                        mma16816(acc[mt][nt], ah[mt], bhp);
                        mma16816(acc[mt][nt], ah[mt], blp);
                        mma16816(acc[mt][nt], al[mt], bhp);
                    }
                }
            }
        }
        __syncthreads();
    }

    // fused epilogue: row softmax over 256 cols
    float* redA = reinterpret_cast<float*>(smem);
    float* redB = redA + 512;

    float rmax[4][2];
#pragma unroll
    for (int mt = 0; mt < 4; mt++) {
#pragma unroll
        for (int h = 0; h < 2; h++) {
            float m = -1e30f;
#pragma unroll
            for (int nt = 0; nt < 8; nt++) {
                m = fmaxf(m, acc[mt][nt][h * 2 + 0]);
                m = fmaxf(m, acc[mt][nt][h * 2 + 1]);
            }
            m = fmaxf(m, __shfl_xor_sync(0xffffffffu, m, 1));
            m = fmaxf(m, __shfl_xor_sync(0xffffffffu, m, 2));
            if (t == 0) redA[(mBase + mt * 16 + h * 8 + g) * 4 + wn] = m;
        }
    }
    __syncthreads();
#pragma unroll
    for (int mt = 0; mt < 4; mt++)
#pragma unroll
        for (int h = 0; h < 2; h++) {
            int row = mBase + mt * 16 + h * 8 + g;
            float m = fmaxf(fmaxf(redA[row * 4], redA[row * 4 + 1]),
                            fmaxf(redA[row * 4 + 2], redA[row * 4 + 3]));
            rmax[mt][h] = m * INV_TEMP;
        }

    float rinv[4][2];
#pragma unroll
    for (int mt = 0; mt < 4; mt++) {
#pragma unroll
        for (int h = 0; h < 2; h++) {
            float s = 0.0f;
#pragma unroll
            for (int nt = 0; nt < 8; nt++) {
#pragma unroll
                for (int e2 = 0; e2 < 2; e2++) {
                    float w = __expf(acc[mt][nt][h * 2 + e2] * INV_TEMP - rmax[mt][h]);
                    acc[mt][nt][h * 2 + e2] = w;
                    s += w;
                }
            }
            s += __shfl_xor_sync(0xffffffffu, s, 1);
            s += __shfl_xor_sync(0xffffffffu, s, 2);
            if (t == 0) redB[(mBase + mt * 16 + h * 8 + g) * 4 + wn] = s;
        }
    }
    __syncthreads();
#pragma unroll
    for (int mt = 0; mt < 4; mt++)
#pragma unroll
        for (int h = 0; h < 2; h++) {
            int row = mBase + mt * 16 + h * 8 + g;
            float s = redB[row * 4] + redB[row * 4 + 1] + redB[row * 4 + 2] + redB[row * 4 + 3];
            rinv[mt][h] = 1.0f / s;
        }

#pragma unroll
    for (int mt = 0; mt < 4; mt++) {
#pragma unroll
        for (int h = 0; h < 2; h++) {
            int j = j0 + mBase + mt * 16 + h * 8 + g;
#pragma unroll
            for (int nt = 0; nt < 8; nt++) {
                int col = nBase + nt * 8 + 2 * t;
                float w0 = acc[mt][nt][h * 2 + 0] * rinv[mt][h];
                float w1 = acc[mt][nt][h * 2 + 1] * rinv[mt][h];
                __nv_bfloat16 h0, l0, h1, l1;
                split_bf16(w0, h0, l0);
                split_bf16(w1, h1, l1);
                size_t o = (size_t)j * C_ + col;
                *reinterpret_cast<uint32_t*>(Ks_hi + o) = pack2(h0, h1);
                *reinterpret_cast<uint32_t*>(Ks_lo + o) = pack2(l0, l1);
            }
        }
    }
}

// ---------------------------------------------------------------------------
// q softmax over hw (rows of 4096), 512 threads: fp32 -> bf16 hi/lo
// ---------------------------------------------------------------------------
__global__ void __launch_bounds__(512) qsoftmax_kernel(
    const float* __restrict__ Qlog,
    __nv_bfloat16* __restrict__ Qs_hi, __nv_bfloat16* __restrict__ Qs_lo)
{
    constexpr int NT = 512, NE = 8;
    const float* row = Qlog + (size_t)blockIdx.x * HW_;
    __shared__ float sred[32];
    const int tid = threadIdx.x;
    const int lane = tid & 31;
    const int wid = tid >> 5;

    float v[NE];
    float m = -1e30f;
#pragma unroll
    for (int e = 0; e < NE; e++) {
        v[e] = row[tid + e * NT] * INV_TEMP;
        m = fmaxf(m, v[e]);
    }
#pragma unroll
    for (int o = 16; o > 0; o >>= 1) m = fmaxf(m, __shfl_xor_sync(0xffffffffu, m, o));
    if (lane == 0) sred[wid] = m;
    __syncthreads();
    if (wid == 0) {
        float tv = (lane < 16) ? sred[lane] : -1e30f;
#pragma unroll
        for (int o = 16; o > 0; o >>= 1) tv = fmaxf(tv, __shfl_xor_sync(0xffffffffu, tv, o));
        if (lane == 0) sred[0] = tv;
    }
    __syncthreads();
    m = sred[0];
    __syncthreads();

    float sum = 0.0f;
#pragma unroll
    for (int e = 0; e < NE; e++) {
        v[e] = __expf(v[e] - m);
        sum += v[e];
    }
#pragma unroll
    for (int o = 16; o > 0; o >>= 1) sum += __shfl_xor_sync(0xffffffffu, sum, o);
    if (lane == 0) sred[wid] = sum;
    __syncthreads();
    if (wid == 0) {
        float tv = (lane < 16) ? sred[lane] : 0.0f;
#pragma unroll
        for (int o = 16; o > 0; o >>= 1) tv += __shfl_xor_sync(0xffffffffu, tv, o);
        if (lane == 0) sred[0] = tv;
    }
    __syncthreads();
    float inv = 1.0f / sred[0];
    size_t base = (size_t)blockIdx.x * HW_;
#pragma unroll
    for (int e = 0; e < NE; e++) {
        float w = v[e] * inv;
        __nv_bfloat16 h, l;
        split_bf16(w, h, l);
        Qs_hi[base + tid + e * NT] = h;
        Qs_lo[base + tid + e * NT] = l;
    }
}

__global__ void zero_kernel(float* __restrict__ p, int n)
{
    int i = blockIdx.x * blockDim.x + threadIdx.x;
    if (i < n) p[i] = 0.0f;
}

// ---------------------------------------------------------------------------
// Launch
// ---------------------------------------------------------------------------
extern "C" void kernel_launch(void* const* d_in, const int* in_sizes, int n_in,
                              void* d_out, int out_size)
{
    (void)in_sizes; (void)n_in; (void)out_size;
    const float* query = (const float*)d_in[0]; // (C, HW)
    const float* key   = (const float*)d_in[1]; // (C, S)
    const float* value = (const float*)d_in[2]; // (C, S)
    const float* Wq    = (const float*)d_in[3]; // (C, C)
    const float* Wk    = (const float*)d_in[4];
    const float* Wv    = (const float*)d_in[5];
    float* out = (float*)d_out;                 // (C, HW)

    static bool s_init = false;
    static cudaStream_t s1, s2;
    static cudaEvent_t evF, evJ1, evJ2;
    if (!s_init) {
        cudaStreamCreateWithFlags(&s1, cudaStreamNonBlocking);
        cudaStreamCreateWithFlags(&s2, cudaStreamNonBlocking);
        cudaEventCreateWithFlags(&evF,  cudaEventDisableTiming);
        cudaEventCreateWithFlags(&evJ1, cudaEventDisableTiming);
        cudaEventCreateWithFlags(&evJ2, cudaEventDisableTiming);
        cudaFuncSetAttribute(gemm_uni_kernel<2, false, true>,  cudaFuncAttributeMaxDynamicSharedMemorySize, GEMM_SMEM);
        cudaFuncSetAttribute(gemm_uni_kernel<2, true,  false>, cudaFuncAttributeMaxDynamicSharedMemorySize, GEMM_SMEM);
        cudaFuncSetAttribute(gemm_uni_kernel<3, false, true>,  cudaFuncAttributeMaxDynamicSharedMemorySize, GEMM_SMEM);
        cudaFuncSetAttribute(gemm_uni_kernel<2, false, false>, cudaFuncAttributeMaxDynamicSharedMemorySize, GEMM_SMEM);
        cudaFuncSetAttribute(gemm_ksm_kernel, cudaFuncAttributeMaxDynamicSharedMemorySize, KSM_SMEM);
        s_init = true;
    }

    __nv_bfloat16 *Ks_hi, *Ks_lo, *Qs_hi, *Qs_lo;
    __nv_bfloat16 *Wq_hi, *Wq_lo, *Wk_hi, *Wk_lo, *Wv_hi, *Wv_lo, *G_hi, *G_lo;
    float *Qlog, *T2;
    cudaGetSymbolAddress((void**)&Ks_hi, g_Ks_hi);
    cudaGetSymbolAddress((void**)&Ks_lo, g_Ks_lo);
    cudaGetSymbolAddress((void**)&Qs_hi, g_Qs_hi);
    cudaGetSymbolAddress((void**)&Qs_lo, g_Qs_lo);
    cudaGetSymbolAddress((void**)&Wq_hi, g_Wq_hi);
    cudaGetSymbolAddress((void**)&Wq_lo, g_Wq_lo);
    cudaGetSymbolAddress((void**)&Wk_hi, g_Wk_hi);
    cudaGetSymbolAddress((void**)&Wk_lo, g_Wk_lo);
    cudaGetSymbolAddress((void**)&Wv_hi, g_Wv_hi);
    cudaGetSymbolAddress((void**)&Wv_lo, g_Wv_lo);
    cudaGetSymbolAddress((void**)&G_hi,  g_G_hi);
    cudaGetSymbolAddress((void**)&G_lo,  g_G_lo);
    cudaGetSymbolAddress((void**)&Qlog,  g_Qlog);
    cudaGetSymbolAddress((void**)&T2,    g_T2);

    // main: weight conversion, then fork
    convW3_kernel<<<dim3(64, 1, 3), 256>>>(Wq, Wk, Wv, Wq_hi, Wq_lo, Wk_hi, Wk_lo, Wv_hi, Wv_lo);
    cudaEventRecord(evF, 0);
    cudaStreamWaitEvent(s1, evF, 0);
    cudaStreamWaitEvent(s2, evF, 0);

    // s1: Ks path (GEMM1 + fused k-softmax)
    gemm_ksm_kernel<<<SA_ / 128, 256, KSM_SMEM, s1>>>(key + S0_, Wk_hi, Wk_lo, Ks_hi, Ks_lo);
    cudaEventRecord(evJ1, s1);

    // s2: Qs path (zero Qlog -> GEMM2 split-K2 atomic -> q softmax)
    zero_kernel<<<(C_ * HW_ + 255) / 256, 256, 0, s2>>>(Qlog, C_ * HW_);
    gemm_uni_kernel<2, false, true><<<dim3(HW_ / 128, C_ / 128, 2), 256, GEMM_SMEM, s2>>>(
        Wq_hi, Wq_lo, nullptr, C_, nullptr, nullptr, query, HW_,
        Qlog, HW_, C_ / 2, nullptr, nullptr);
    qsoftmax_kernel<<<C_, 512, 0, s2>>>(Qlog, Qs_hi, Qs_lo);
    cudaEventRecord(evJ2, s2);

    // main: zero T2 and out (overlaps with both branches)
    zero_kernel<<<(C_ * C_ + 255) / 256, 256>>>(T2, C_ * C_);
    zero_kernel<<<(C_ * HW_ + 255) / 256, 256>>>(out, C_ * HW_);

    // join Ks path -> GEMM3, GEMM4
    cudaStreamWaitEvent(0, evJ1, 0);
    gemm_uni_kernel<2, true, false><<<dim3(C_ / 128, C_ / 128, 32), 256, GEMM_SMEM>>>(
        nullptr, nullptr, value + S0_, S_, Ks_hi, Ks_lo, nullptr, C_,
        T2, C_, SA_ / 32, nullptr, nullptr);
    gemm_uni_kernel<3, false, true><<<dim3(C_ / 128, C_ / 128, 1), 256, GEMM_SMEM>>>(
        Wv_hi, Wv_lo, nullptr, C_, nullptr, nullptr, T2, C_,
        nullptr, C_, C_, G_hi, G_lo);

    // join Qs path -> GEMM5 split-K2 atomic into zeroed out
    cudaStreamWaitEvent(0, evJ2, 0);
    gemm_uni_kernel<2, false, false><<<dim3(HW_ / 128, C_ / 128, 2), 256, GEMM_SMEM>>>(
        G_hi, G_lo, nullptr, C_, Qs_hi, Qs_lo, nullptr, HW_,
        out, HW_, C_ / 2, nullptr, nullptr);
}

// round 7
// speedup vs baseline: 1.4829x; 1.1733x over previous
#include <cuda_runtime.h>
#include <cuda_bf16.h>
#include <cstdint>

// ---------------------------------------------------------------------------
// Problem constants (B=1)
// ---------------------------------------------------------------------------
static constexpr int C_   = 256;
static constexpr int HW_  = 4096;     // 64*64
static constexpr int S_   = 32768;    // 8*64*64
static constexpr int SA_  = 20480;    // 5*64*64 active (last 5 frames)
static constexpr int S0_  = S_ - SA_; // 12288
static constexpr float INV_TEMP = 10.0f;

// ---------------------------------------------------------------------------
// Device scratch
// ---------------------------------------------------------------------------
__device__ __align__(16) __nv_bfloat16 g_Ks_hi [SA_ * C_];   // [j][o]  (k-softmaxed)
__device__ __align__(16) __nv_bfloat16 g_Ks_lo [SA_ * C_];
__device__ __align__(16) __nv_bfloat16 g_Qs_hi [C_ * HW_];   // [o][hw] (q-softmaxed)
__device__ __align__(16) __nv_bfloat16 g_Qs_lo [C_ * HW_];
__device__ __align__(16) __nv_bfloat16 g_Wq_hi[C_ * C_], g_Wq_lo[C_ * C_];
__device__ __align__(16) __nv_bfloat16 g_Wk_hi[C_ * C_], g_Wk_lo[C_ * C_];
__device__ __align__(16) __nv_bfloat16 g_Wv_hi[C_ * C_], g_Wv_lo[C_ * C_];
__device__ __align__(16) float g_Qlog[C_ * HW_];   // q logits (split-K accumulator)
__device__ __align__(16) float g_T2  [C_ * C_];    // split-K accumulator [a][o]
__device__ __align__(16) float g_G   [C_ * C_];    // split-K accumulator [c][o]

// ---------------------------------------------------------------------------
// PTX helpers (compute_100-safe)
// ---------------------------------------------------------------------------
__device__ __forceinline__ uint32_t smem_u32(const void* p) {
    uint32_t a;
    asm("{ .reg .u64 t; cvta.to.shared.u64 t, %1; cvt.u32.u64 %0, t; }" : "=r"(a) : "l"(p));
    return a;
}
__device__ __forceinline__ void cp16(uint32_t dst, const void* src) {
    asm volatile("cp.async.cg.shared.global [%0], [%1], 16;" :: "r"(dst), "l"(src));
}
__device__ __forceinline__ void cp_commit() {
    asm volatile("cp.async.commit_group;" ::: "memory");
}
template<int N>
__device__ __forceinline__ void cp_wait() {
    asm volatile("cp.async.wait_group %0;" :: "n"(N) : "memory");
}
__device__ __forceinline__ void ldm_x4(uint32_t* r, uint32_t addr) {
    asm volatile("ldmatrix.sync.aligned.m8n8.x4.shared.b16 {%0,%1,%2,%3}, [%4];"
                 : "=r"(r[0]), "=r"(r[1]), "=r"(r[2]), "=r"(r[3]) : "r"(addr));
}
__device__ __forceinline__ void ldm_x4_t(uint32_t* r, uint32_t addr) {
    asm volatile("ldmatrix.sync.aligned.m8n8.x4.trans.shared.b16 {%0,%1,%2,%3}, [%4];"
                 : "=r"(r[0]), "=r"(r[1]), "=r"(r[2]), "=r"(r[3]) : "r"(addr));
}
__device__ __forceinline__ void mma16816(float* c, const uint32_t* a, const uint32_t* b) {
    asm volatile(
        "mma.sync.aligned.m16n8k16.row.col.f32.bf16.bf16.f32 "
        "{%0,%1,%2,%3}, {%4,%5,%6,%7}, {%8,%9}, {%0,%1,%2,%3};"
        : "+f"(c[0]), "+f"(c[1]), "+f"(c[2]), "+f"(c[3])
        : "r"(a[0]), "r"(a[1]), "r"(a[2]), "r"(a[3]), "r"(b[0]), "r"(b[1]));
}
__device__ __forceinline__ void split_bf16(float v, __nv_bfloat16& h, __nv_bfloat16& l) {
    h = __float2bfloat16(v);
    l = __float2bfloat16(v - __bfloat162float(h));
}
__device__ __forceinline__ uint32_t pack2(__nv_bfloat16 a, __nv_bfloat16 b) {
    return (uint32_t)__bfloat16_as_ushort(a) | ((uint32_t)__bfloat16_as_ushort(b) << 16);
}
__device__ __forceinline__ void split4(float4 v, uint2& ph, uint2& pl) {
    __nv_bfloat16 h0, l0, h1, l1, h2, l2, h3, l3;
    split_bf16(v.x, h0, l0); split_bf16(v.y, h1, l1);
    split_bf16(v.z, h2, l2); split_bf16(v.w, h3, l3);
    ph = make_uint2(pack2(h0, h1), pack2(h2, h3));
    pl = make_uint2(pack2(l0, l1), pack2(l2, l3));
}

// ---------------------------------------------------------------------------
// 3 weight matrices (256x256) fp32 -> bf16 hi/lo, one launch via grid.z
// ---------------------------------------------------------------------------
__global__ void convW3_kernel(const float* __restrict__ s0, const float* __restrict__ s1,
                              const float* __restrict__ s2,
                              __nv_bfloat16* __restrict__ h0, __nv_bfloat16* __restrict__ l0,
                              __nv_bfloat16* __restrict__ h1, __nv_bfloat16* __restrict__ l1,
                              __nv_bfloat16* __restrict__ h2, __nv_bfloat16* __restrict__ l2)
{
    const float* src = (blockIdx.z == 0) ? s0 : (blockIdx.z == 1) ? s1 : s2;
    __nv_bfloat16* hi = (blockIdx.z == 0) ? h0 : (blockIdx.z == 1) ? h1 : h2;
    __nv_bfloat16* lo = (blockIdx.z == 0) ? l0 : (blockIdx.z == 1) ? l1 : l2;
    int idx = blockIdx.x * blockDim.x + threadIdx.x;
    float4 v = *reinterpret_cast<const float4*>(src + idx * 4);
    uint2 ph, pl;
    split4(v, ph, pl);
    *reinterpret_cast<uint2*>(hi + idx * 4) = ph;
    *reinterpret_cast<uint2*>(lo + idx * 4) = pl;
}

// ---------------------------------------------------------------------------
// Generic tensor-core GEMM:  D[m,n] += sum_k A[m,k]*B[n,k], bf16x3 split.
// A: normal layout (rows m, k contiguous): bf16 pair (!AF32) or fp32 (AF32).
// B: TRANS source layout [k][n]: bf16 pair (!BF32) or fp32 (BF32).
// fp32 sides: LDG->reg prefetch -> in-reg split -> STS (no staging smem).
// BM=BN=128, BK=32, 256 threads, 2-stage, 2 CTAs/SM. Epilogue: fp32 atomicAdd.
// ---------------------------------------------------------------------------
static constexpr int ABUF = 10240;   // 128 x 80
static constexpr int BBUF = 8704;    // 32 x 272
static constexpr int OFF_B = 4 * ABUF;             // 40960
static constexpr int GEMM_SMEM = OFF_B + 4 * BBUF; // 75776

template<bool AF32, bool BF32>
__global__ void __launch_bounds__(256, 2) gemm_uni_kernel(
    const __nv_bfloat16* __restrict__ Ah, const __nv_bfloat16* __restrict__ Al,
    const float* __restrict__ Af, int aLd,
    const __nv_bfloat16* __restrict__ Bh, const __nv_bfloat16* __restrict__ Bl,
    const float* __restrict__ Bf, int bLd,
    float* __restrict__ out, int outLd, int kPerCta)
{
    extern __shared__ char smem[];
    uint32_t sb = smem_u32(smem);
    const int tid  = threadIdx.x;
    const int wid  = tid >> 5;
    const int lane = tid & 31;
    const int m0 = blockIdx.y * 128;
    const int n0 = blockIdx.x * 128;
    const int kStart = blockIdx.z * kPerCta;
    const int nChunks = kPerCta >> 5;

    const int wm = wid >> 2, wn = wid & 3;
    const int mBase = wm * 64, nBase = wn * 32;
    const int g = lane >> 2, t = lane & 3;
    const int mat = lane >> 3, r = lane & 7;

    const uint32_t aFrag = (uint32_t)(mBase + (mat & 1) * 8 + r) * 80 + (mat >> 1) * 16;
    const uint32_t bFrag = (uint32_t)((mat & 1) * 8 + r) * 272 + (nBase + (mat >> 1) * 8) * 2;

    float acc[4][4][4];
#pragma unroll
    for (int i = 0; i < 4; i++)
#pragma unroll
        for (int j = 0; j < 4; j++)
#pragma unroll
            for (int e = 0; e < 4; e++) acc[i][j][e] = 0.0f;

    float4 afb[4], bfb[4];

    auto ldg_f32 = [&](int kOff) {
        if (AF32) {
#pragma unroll
            for (int i = 0; i < 4; i++) {
                int slot = tid + i * 256;
                afb[i] = *reinterpret_cast<const float4*>(
                    Af + (size_t)(m0 + (slot >> 3)) * aLd + kOff + (slot & 7) * 4);
            }
        }
        if (BF32) {
#pragma unroll
            for (int i = 0; i < 4; i++) {
                int slot = tid + i * 256;
                bfb[i] = *reinterpret_cast<const float4*>(
                    Bf + (size_t)(kOff + (slot >> 5)) * bLd + n0 + (slot & 31) * 4);
            }
        }
    };
    auto sts_f32 = [&](int st) {
        if (AF32) {
#pragma unroll
            for (int i = 0; i < 4; i++) {
                int slot = tid + i * 256;
                int row = slot >> 3, c4 = (slot & 7) * 4;
                uint2 ph, pl;
                split4(afb[i], ph, pl);
                *reinterpret_cast<uint2*>(smem + (st * 2 + 0) * ABUF + row * 80 + c4 * 2) = ph;
                *reinterpret_cast<uint2*>(smem + (st * 2 + 1) * ABUF + row * 80 + c4 * 2) = pl;
            }
        }
        if (BF32) {
#pragma unroll
            for (int i = 0; i < 4; i++) {
                int slot = tid + i * 256;
                int row = slot >> 5, c4 = (slot & 31) * 4;
                uint2 ph, pl;
                split4(bfb[i], ph, pl);
                *reinterpret_cast<uint2*>(smem + OFF_B + (st * 2 + 0) * BBUF + row * 272 + c4 * 2) = ph;
                *reinterpret_cast<uint2*>(smem + OFF_B + (st * 2 + 1) * BBUF + row * 272 + c4 * 2) = pl;
            }
        }
    };
    auto cpa = [&](int st, int kOff) {
        if (!AF32) {
#pragma unroll
            for (int i = 0; i < 4; i++) {
                int idx = tid + i * 256;
                int hl = idx >> 9, rem = idx & 511;
                int row = rem >> 2, ch = rem & 3;
                cp16(sb + (st * 2 + hl) * ABUF + row * 80 + ch * 16,
                     (hl ? Al : Ah) + (size_t)(m0 + row) * aLd + kOff + ch * 8);
            }
        }
        if (!BF32) {
#pragma unroll
            for (int i = 0; i < 4; i++) {
                int idx = tid + i * 256;
                int hl = idx >> 9, rem = idx & 511;
                int row = rem >> 4, ch = rem & 15;
                cp16(sb + OFF_B + (st * 2 + hl) * BBUF + row * 272 + ch * 16,
                     (hl ? Bl : Bh) + (size_t)(kOff + row) * bLd + n0 + ch * 8);
            }
        }
    };

    cpa(0, kStart);
    cp_commit();
    ldg_f32(kStart);
    if (nChunks > 1) { cpa(1, kStart + 32); cp_commit(); }

    for (int ch = 0; ch < nChunks; ch++) {
        const int st = ch & 1;
        sts_f32(st);
        if (ch + 1 < nChunks) cp_wait<1>(); else cp_wait<0>();
        __syncthreads();
        if (ch + 1 < nChunks) ldg_f32(kStart + (ch + 1) * 32);

        const uint32_t aHiB = sb + (st * 2 + 0) * ABUF;
        const uint32_t aLoB = sb + (st * 2 + 1) * ABUF;
        const uint32_t bHiB = sb + OFF_B + (st * 2 + 0) * BBUF;
        const uint32_t bLoB = sb + OFF_B + (st * 2 + 1) * BBUF;
#pragma unroll
        for (int kk = 0; kk < 2; kk++) {
            uint32_t bh[8], bl[8];
#pragma unroll
            for (int p = 0; p < 2; p++) {
                ldm_x4_t(&bh[p * 4], bHiB + bFrag + kk * 4352 + p * 32);
                ldm_x4_t(&bl[p * 4], bLoB + bFrag + kk * 4352 + p * 32);
            }
#pragma unroll
            for (int mt = 0; mt < 4; mt++) {
                uint32_t ah[4], al[4];
                ldm_x4(ah, aHiB + aFrag + mt * 1280 + kk * 32);
                ldm_x4(al, aLoB + aFrag + mt * 1280 + kk * 32);
#pragma unroll
                for (int nt = 0; nt < 4; nt++) {
                    const uint32_t* bhp = &bh[(nt >> 1) * 4 + (nt & 1) * 2];
                    const uint32_t* blp = &bl[(nt >> 1) * 4 + (nt & 1) * 2];
                    mma16816(acc[mt][nt], ah, bhp);
                    mma16816(acc[mt][nt], ah, blp);
                    mma16816(acc[mt][nt], al, bhp);
                }
            }
        }
        __syncthreads();
        if (ch + 2 < nChunks) { cpa(st, kStart + (ch + 2) * 32); cp_commit(); }
    }

#pragma unroll
    for (int mt = 0; mt < 4; mt++) {
#pragma unroll
        for (int nt = 0; nt < 4; nt++) {
            int row = m0 + mBase + mt * 16 + g;
            int col = n0 + nBase + nt * 8 + 2 * t;
            float* p0 = out + (size_t)row * outLd + col;
            float* p1 = out + (size_t)(row + 8) * outLd + col;
            atomicAdd(p0,     acc[mt][nt][0]);
            atomicAdd(p0 + 1, acc[mt][nt][1]);
            atomicAdd(p1,     acc[mt][nt][2]);
            atomicAdd(p1 + 1, acc[mt][nt][3]);
        }
    }
}

// ---------------------------------------------------------------------------
// GEMM1 fused: Klog[j][o] = sum_c key[c][j]*Wk[o][c], then k-softmax over o,
// store Ks [j][o] bf16 hi/lo row-major. A fp32 trans via reg-convert.
// ---------------------------------------------------------------------------
static constexpr int KSM_BBUF  = 20480;                 // 256 x 80
static constexpr int KSM_OFF_A = 4 * KSM_BBUF;          // 81920
static constexpr int KSM_ABUF  = 8704;                  // 32 x 272
static constexpr int KSM_SMEM  = KSM_OFF_A + 4 * KSM_ABUF;   // 116736

__global__ void __launch_bounds__(256, 1) gemm_ksm_kernel(
    const float* __restrict__ keyP,          // key + S0_, ld = S_
    const __nv_bfloat16* __restrict__ Bh, const __nv_bfloat16* __restrict__ Bl,
    __nv_bfloat16* __restrict__ Ks_hi, __nv_bfloat16* __restrict__ Ks_lo)
{
    extern __shared__ char smem[];
    uint32_t sb = smem_u32(smem);
    const int tid  = threadIdx.x;
    const int wid  = tid >> 5;
    const int lane = tid & 31;
    const int j0 = blockIdx.x * 128;

    const int wm = wid >> 2, wn = wid & 3;
    const int mBase = wm * 64, nBase = wn * 64;
    const int g = lane >> 2, t = lane & 3;
    const int mat = lane >> 3, r = lane & 7;

    const uint32_t aFragT = (uint32_t)((mat >> 1) * 8 + r) * 272 + (mBase + (mat & 1) * 8) * 2;
    const uint32_t bFrag = (uint32_t)(nBase + (mat >> 1) * 8 + r) * 80 + (mat & 1) * 16;

    float acc[4][8][4];
#pragma unroll
    for (int i = 0; i < 4; i++)
#pragma unroll
        for (int j = 0; j < 8; j++)
#pragma unroll
            for (int e = 0; e < 4; e++) acc[i][j][e] = 0.0f;

    float4 afb[4];
    auto ldg_a = [&](int kOff) {
#pragma unroll
        for (int i = 0; i < 4; i++) {
            int slot = tid + i * 256;
            afb[i] = *reinterpret_cast<const float4*>(
                keyP + (size_t)(kOff + (slot >> 5)) * S_ + j0 + (slot & 31) * 4);
        }
    };
    auto sts_a = [&](int st) {
#pragma unroll
        for (int i = 0; i < 4; i++) {
            int slot = tid + i * 256;
            int row = slot >> 5, c4 = (slot & 31) * 4;
            uint2 ph, pl;
            split4(afb[i], ph, pl);
            *reinterpret_cast<uint2*>(smem + KSM_OFF_A + (st * 2 + 0) * KSM_ABUF + row * 272 + c4 * 2) = ph;
            *reinterpret_cast<uint2*>(smem + KSM_OFF_A + (st * 2 + 1) * KSM_ABUF + row * 272 + c4 * 2) = pl;
        }
    };
    auto cpb = [&](int st, int kOff) {
#pragma unroll
        for (int i = 0; i < 8; i++) {
            int idx = tid + i * 256;
            int hl = idx >> 10, rem = idx & 1023;
            int row = rem >> 2, ch = rem & 3;
            cp16(sb + (st * 2 + hl) * KSM_BBUF + row * 80 + ch * 16,
                 (hl ? Bl : Bh) + (size_t)row * C_ + kOff + ch * 8);
        }
    };

    cpb(0, 0);
    cp_commit();
    ldg_a(0);
    cpb(1, 32);
    cp_commit();

    const int nChunks = 8;
    for (int ch = 0; ch < nChunks; ch++) {
        const int st = ch & 1;
        sts_a(st);
        if (ch + 1 < nChunks) cp_wait<1>(); else cp_wait<0>();
        __syncthreads();
        if (ch + 1 < nChunks) ldg_a((ch + 1) * 32);

        const uint32_t aHiB = sb + KSM_OFF_A + (st * 2 + 0) * KSM_ABUF;
        const uint32_t aLoB = sb + KSM_OFF_A + (st * 2 + 1) * KSM_ABUF;
        const uint32_t bHiB = sb + (st * 2 + 0) * KSM_BBUF;
        const uint32_t bLoB = sb + (st * 2 + 1) * KSM_BBUF;
#pragma unroll
        for (int kk = 0; kk < 2; kk++) {
            uint32_t ah[4][4], al[4][4];
#pragma unroll
            for (int mt = 0; mt < 4; mt++) {
                ldm_x4_t(ah[mt], aHiB + aFragT + kk * 4352 + mt * 32);
                ldm_x4_t(al[mt], aLoB + aFragT + kk * 4352 + mt * 32);
            }
#pragma unroll
            for (int ph = 0; ph < 2; ph++) {
                uint32_t bh8[8], bl8[8];
#pragma unroll
                for (int pl = 0; pl < 2; pl++) {
                    ldm_x4(&bh8[pl * 4], bHiB + bFrag + (ph * 2 + pl) * 1280 + kk * 32);
                    ldm_x4(&bl8[pl * 4], bLoB + bFrag + (ph * 2 + pl) * 1280 + kk * 32);
                }
#pragma unroll
                for (int mt = 0; mt < 4; mt++) {
#pragma unroll
                    for (int l = 0; l < 4; l++) {
                        const uint32_t* bhp = &bh8[(l >> 1) * 4 + (l & 1) * 2];
                        const uint32_t* blp = &bl8[(l >> 1) * 4 + (l & 1) * 2];
                        int nt = ph * 4 + l;
                        mma16816(acc[mt][nt], ah[mt], bhp);
                        mma16816(acc[mt][nt], ah[mt], blp);
                        mma16816(acc[mt][nt], al[mt], bhp);
                    }
                }
            }
        }
        __syncthreads();
        if (ch + 2 < nChunks) { cpb(st, (ch + 2) * 32); cp_commit(); }
    }

    // fused epilogue: row softmax over 256 cols
    float* redA = reinterpret_cast<float*>(smem);
    float* redB = redA + 512;

    float rmax[4][2];
#pragma unroll
    for (int mt = 0; mt < 4; mt++) {
#pragma unroll
        for (int h = 0; h < 2; h++) {
            float m = -1e30f;
#pragma unroll
            for (int nt = 0; nt < 8; nt++) {
                m = fmaxf(m, acc[mt][nt][h * 2 + 0]);
                m = fmaxf(m, acc[mt][nt][h * 2 + 1]);
            }
            m = fmaxf(m, __shfl_xor_sync(0xffffffffu, m, 1));
            m = fmaxf(m, __shfl_xor_sync(0xffffffffu, m, 2));
            if (t == 0) redA[(mBase + mt * 16 + h * 8 + g) * 4 + wn] = m;
        }
    }
    __syncthreads();
#pragma unroll
    for (int mt = 0; mt < 4; mt++)
#pragma unroll
        for (int h = 0; h < 2; h++) {
            int row = mBase + mt * 16 + h * 8 + g;
            float m = fmaxf(fmaxf(redA[row * 4], redA[row * 4 + 1]),
                            fmaxf(redA[row * 4 + 2], redA[row * 4 + 3]));
            rmax[mt][h] = m * INV_TEMP;
        }

    float rinv[4][2];
#pragma unroll
    for (int mt = 0; mt < 4; mt++) {
#pragma unroll
        for (int h = 0; h < 2; h++) {
            float s = 0.0f;
#pragma unroll
            for (int nt = 0; nt < 8; nt++) {
#pragma unroll
                for (int e2 = 0; e2 < 2; e2++) {
                    float w = __expf(acc[mt][nt][h * 2 + e2] * INV_TEMP - rmax[mt][h]);
                    acc[mt][nt][h * 2 + e2] = w;
                    s += w;
                }
            }
            s += __shfl_xor_sync(0xffffffffu, s, 1);
            s += __shfl_xor_sync(0xffffffffu, s, 2);
            if (t == 0) redB[(mBase + mt * 16 + h * 8 + g) * 4 + wn] = s;
        }
    }
    __syncthreads();
#pragma unroll
    for (int mt = 0; mt < 4; mt++)
#pragma unroll
        for (int h = 0; h < 2; h++) {
            int row = mBase + mt * 16 + h * 8 + g;
            float s = redB[row * 4] + redB[row * 4 + 1] + redB[row * 4 + 2] + redB[row * 4 + 3];
            rinv[mt][h] = 1.0f / s;
        }

#pragma unroll
    for (int mt = 0; mt < 4; mt++) {
#pragma unroll
        for (int h = 0; h < 2; h++) {
            int j = j0 + mBase + mt * 16 + h * 8 + g;
#pragma unroll
            for (int nt = 0; nt < 8; nt++) {
                int col = nBase + nt * 8 + 2 * t;
                float w0 = acc[mt][nt][h * 2 + 0] * rinv[mt][h];
                float w1 = acc[mt][nt][h * 2 + 1] * rinv[mt][h];
                __nv_bfloat16 h0, l0, h1, l1;
                split_bf16(w0, h0, l0);
                split_bf16(w1, h1, l1);
                size_t o = (size_t)j * C_ + col;
                *reinterpret_cast<uint32_t*>(Ks_hi + o) = pack2(h0, h1);
                *reinterpret_cast<uint32_t*>(Ks_lo + o) = pack2(l0, l1);
            }
        }
    }
}

// ---------------------------------------------------------------------------
// q softmax over hw (rows of 4096), 512 threads: fp32 -> bf16 hi/lo
// ---------------------------------------------------------------------------
__global__ void __launch_bounds__(512) qsoftmax_kernel(
    const float* __restrict__ Qlog,
    __nv_bfloat16* __restrict__ Qs_hi, __nv_bfloat16* __restrict__ Qs_lo)
{
    constexpr int NT = 512, NE = 8;
    const float* row = Qlog + (size_t)blockIdx.x * HW_;
    __shared__ float sred[32];
    const int tid = threadIdx.x;
    const int lane = tid & 31;
    const int wid = tid >> 5;

    float v[NE];
    float m = -1e30f;
#pragma unroll
    for (int e = 0; e < NE; e++) {
        v[e] = row[tid + e * NT] * INV_TEMP;
        m = fmaxf(m, v[e]);
    }
#pragma unroll
    for (int o = 16; o > 0; o >>= 1) m = fmaxf(m, __shfl_xor_sync(0xffffffffu, m, o));
    if (lane == 0) sred[wid] = m;
    __syncthreads();
    if (wid == 0) {
        float tv = (lane < 16) ? sred[lane] : -1e30f;
#pragma unroll
        for (int o = 16; o > 0; o >>= 1) tv = fmaxf(tv, __shfl_xor_sync(0xffffffffu, tv, o));
        if (lane == 0) sred[0] = tv;
    }
    __syncthreads();
    m = sred[0];
    __syncthreads();

    float sum = 0.0f;
#pragma unroll
    for (int e = 0; e < NE; e++) {
        v[e] = __expf(v[e] - m);
        sum += v[e];
    }
#pragma unroll
    for (int o = 16; o > 0; o >>= 1) sum += __shfl_xor_sync(0xffffffffu, sum, o);
    if (lane == 0) sred[wid] = sum;
    __syncthreads();
    if (wid == 0) {
        float tv = (lane < 16) ? sred[lane] : 0.0f;
#pragma unroll
        for (int o = 16; o > 0; o >>= 1) tv += __shfl_xor_sync(0xffffffffu, tv, o);
        if (lane == 0) sred[0] = tv;
    }
    __syncthreads();
    float inv = 1.0f / sred[0];
    size_t base = (size_t)blockIdx.x * HW_;
#pragma unroll
    for (int e = 0; e < NE; e++) {
        float w = v[e] * inv;
        __nv_bfloat16 h, l;
        split_bf16(w, h, l);
        Qs_hi[base + tid + e * NT] = h;
        Qs_lo[base + tid + e * NT] = l;
    }
}

__global__ void zero_kernel(float* __restrict__ p, int n)
{
    int i = blockIdx.x * blockDim.x + threadIdx.x;
    if (i < n) p[i] = 0.0f;
}

// ---------------------------------------------------------------------------
// Launch
// ---------------------------------------------------------------------------
extern "C" void kernel_launch(void* const* d_in, const int* in_sizes, int n_in,
                              void* d_out, int out_size)
{
    (void)in_sizes; (void)n_in; (void)out_size;
    const float* query = (const float*)d_in[0]; // (C, HW)
    const float* key   = (const float*)d_in[1]; // (C, S)
    const float* value = (const float*)d_in[2]; // (C, S)
    const float* Wq    = (const float*)d_in[3]; // (C, C)
    const float* Wk    = (const float*)d_in[4];
    const float* Wv    = (const float*)d_in[5];
    float* out = (float*)d_out;                 // (C, HW)

    static bool s_init = false;
    static cudaStream_t s1, s2;
    static cudaEvent_t evF, evJ1, evJ2;
    if (!s_init) {
        cudaStreamCreateWithFlags(&s1, cudaStreamNonBlocking);
        cudaStreamCreateWithFlags(&s2, cudaStreamNonBlocking);
        cudaEventCreateWithFlags(&evF,  cudaEventDisableTiming);
        cudaEventCreateWithFlags(&evJ1, cudaEventDisableTiming);
        cudaEventCreateWithFlags(&evJ2, cudaEventDisableTiming);
        cudaFuncSetAttribute(gemm_uni_kernel<false, true>, cudaFuncAttributeMaxDynamicSharedMemorySize, GEMM_SMEM);
        cudaFuncSetAttribute(gemm_uni_kernel<true, false>, cudaFuncAttributeMaxDynamicSharedMemorySize, GEMM_SMEM);
        cudaFuncSetAttribute(gemm_ksm_kernel, cudaFuncAttributeMaxDynamicSharedMemorySize, KSM_SMEM);
        s_init = true;
    }

    __nv_bfloat16 *Ks_hi, *Ks_lo, *Qs_hi, *Qs_lo;
    __nv_bfloat16 *Wq_hi, *Wq_lo, *Wk_hi, *Wk_lo, *Wv_hi, *Wv_lo;
    float *Qlog, *T2, *G;
    cudaGetSymbolAddress((void**)&Ks_hi, g_Ks_hi);
    cudaGetSymbolAddress((void**)&Ks_lo, g_Ks_lo);
    cudaGetSymbolAddress((void**)&Qs_hi, g_Qs_hi);
    cudaGetSymbolAddress((void**)&Qs_lo, g_Qs_lo);
    cudaGetSymbolAddress((void**)&Wq_hi, g_Wq_hi);
    cudaGetSymbolAddress((void**)&Wq_lo, g_Wq_lo);
    cudaGetSymbolAddress((void**)&Wk_hi, g_Wk_hi);
    cudaGetSymbolAddress((void**)&Wk_lo, g_Wk_lo);
    cudaGetSymbolAddress((void**)&Wv_hi, g_Wv_hi);
    cudaGetSymbolAddress((void**)&Wv_lo, g_Wv_lo);
    cudaGetSymbolAddress((void**)&Qlog,  g_Qlog);
    cudaGetSymbolAddress((void**)&T2,    g_T2);
    cudaGetSymbolAddress((void**)&G,     g_G);

    // main: weight conversion, then fork
    convW3_kernel<<<dim3(64, 1, 3), 256>>>(Wq, Wk, Wv, Wq_hi, Wq_lo, Wk_hi, Wk_lo, Wv_hi, Wv_lo);
    cudaEventRecord(evF, 0);
    cudaStreamWaitEvent(s1, evF, 0);
    cudaStreamWaitEvent(s2, evF, 0);

    // s1: Ks path (GEMM1 + fused k-softmax)
    gemm_ksm_kernel<<<SA_ / 128, 256, KSM_SMEM, s1>>>(key + S0_, Wk_hi, Wk_lo, Ks_hi, Ks_lo);
    cudaEventRecord(evJ1, s1);

    // s2: Qs path
    zero_kernel<<<(C_ * HW_ + 255) / 256, 256, 0, s2>>>(Qlog, C_ * HW_);
    gemm_uni_kernel<false, true><<<dim3(HW_ / 128, C_ / 128, 2), 256, GEMM_SMEM, s2>>>(
        Wq_hi, Wq_lo, nullptr, C_, nullptr, nullptr, query, HW_, Qlog, HW_, C_ / 2);
    qsoftmax_kernel<<<C_, 512, 0, s2>>>(Qlog, Qs_hi, Qs_lo);
    cudaEventRecord(evJ2, s2);

    // main: zero accumulators (overlaps both branches)
    zero_kernel<<<(C_ * C_ + 255) / 256, 256>>>(T2, C_ * C_);
    zero_kernel<<<(C_ * C_ + 255) / 256, 256>>>(G, C_ * C_);
    zero_kernel<<<(C_ * HW_ + 255) / 256, 256>>>(out, C_ * HW_);

    // join Ks path -> GEMM3 (T2), GEMM4 (G)
    cudaStreamWaitEvent(0, evJ1, 0);
    gemm_uni_kernel<true, false><<<dim3(C_ / 128, C_ / 128, 32), 256, GEMM_SMEM>>>(
        nullptr, nullptr, value + S0_, S_, Ks_hi, Ks_lo, nullptr, C_, T2, C_, SA_ / 32);
    gemm_uni_kernel<false, true><<<dim3(C_ / 128, C_ / 128, 8), 256, GEMM_SMEM>>>(
        Wv_hi, Wv_lo, nullptr, C_, nullptr, nullptr, T2, C_, G, C_, C_ / 8);

    // join Qs path -> GEMM5
    cudaStreamWaitEvent(0, evJ2, 0);
    gemm_uni_kernel<true, false><<<dim3(HW_ / 128, C_ / 128, 2), 256, GEMM_SMEM>>>(
        nullptr, nullptr, G, C_, Qs_hi, Qs_lo, nullptr, HW_, out, HW_, C_ / 2);
}

// round 8
// speedup vs baseline: 1.5044x; 1.0145x over previous
#include <cuda_runtime.h>
#include <cuda_bf16.h>
#include <cstdint>

// ---------------------------------------------------------------------------
// Problem constants (B=1)
// ---------------------------------------------------------------------------
static constexpr int C_   = 256;
static constexpr int HW_  = 4096;     // 64*64
static constexpr int S_   = 32768;    // 8*64*64
static constexpr int SA_  = 20480;    // 5*64*64 active (last 5 frames)
static constexpr int S0_  = S_ - SA_; // 12288
static constexpr float INV_TEMP = 10.0f;

// ---------------------------------------------------------------------------
// Device scratch
// ---------------------------------------------------------------------------
__device__ __align__(16) __nv_bfloat16 g_Ks_hi [SA_ * C_];   // [j][o]  (k-softmaxed)
__device__ __align__(16) __nv_bfloat16 g_Ks_lo [SA_ * C_];
__device__ __align__(16) __nv_bfloat16 g_Qs_hi [C_ * HW_];   // [o][hw] (q-softmaxed)
__device__ __align__(16) __nv_bfloat16 g_Qs_lo [C_ * HW_];
__device__ __align__(16) __nv_bfloat16 g_Wq_hi[C_ * C_], g_Wq_lo[C_ * C_];
__device__ __align__(16) __nv_bfloat16 g_Wk_hi[C_ * C_], g_Wk_lo[C_ * C_];
__device__ __align__(16) __nv_bfloat16 g_Wv_hi[C_ * C_], g_Wv_lo[C_ * C_];
__device__ __align__(16) float g_Qlog[C_ * HW_];   // q logits (split-K accumulator)
__device__ __align__(16) float g_T2  [C_ * C_];    // split-K accumulator [a][o]
__device__ __align__(16) float g_G   [C_ * C_];    // split-K accumulator [c][o]

// ---------------------------------------------------------------------------
// PTX helpers (compute_100-safe)
// ---------------------------------------------------------------------------
__device__ __forceinline__ uint32_t smem_u32(const void* p) {
    uint32_t a;
    asm("{ .reg .u64 t; cvta.to.shared.u64 t, %1; cvt.u32.u64 %0, t; }" : "=r"(a) : "l"(p));
    return a;
}
__device__ __forceinline__ void cp16(uint32_t dst, const void* src) {
    asm volatile("cp.async.cg.shared.global [%0], [%1], 16;" :: "r"(dst), "l"(src));
}
__device__ __forceinline__ void cp_commit() {
    asm volatile("cp.async.commit_group;" ::: "memory");
}
template<int N>
__device__ __forceinline__ void cp_wait() {
    asm volatile("cp.async.wait_group %0;" :: "n"(N) : "memory");
}
__device__ __forceinline__ void ldm_x4(uint32_t* r, uint32_t addr) {
    asm volatile("ldmatrix.sync.aligned.m8n8.x4.shared.b16 {%0,%1,%2,%3}, [%4];"
                 : "=r"(r[0]), "=r"(r[1]), "=r"(r[2]), "=r"(r[3]) : "r"(addr));
}
__device__ __forceinline__ void ldm_x4_t(uint32_t* r, uint32_t addr) {
    asm volatile("ldmatrix.sync.aligned.m8n8.x4.trans.shared.b16 {%0,%1,%2,%3}, [%4];"
                 : "=r"(r[0]), "=r"(r[1]), "=r"(r[2]), "=r"(r[3]) : "r"(addr));
}
__device__ __forceinline__ void mma16816(float* c, const uint32_t* a, const uint32_t* b) {
    asm volatile(
        "mma.sync.aligned.m16n8k16.row.col.f32.bf16.bf16.f32 "
        "{%0,%1,%2,%3}, {%4,%5,%6,%7}, {%8,%9}, {%0,%1,%2,%3};"
        : "+f"(c[0]), "+f"(c[1]), "+f"(c[2]), "+f"(c[3])
        : "r"(a[0]), "r"(a[1]), "r"(a[2]), "r"(a[3]), "r"(b[0]), "r"(b[1]));
}
__device__ __forceinline__ void split_bf16(float v, __nv_bfloat16& h, __nv_bfloat16& l) {
    h = __float2bfloat16(v);
    l = __float2bfloat16(v - __bfloat162float(h));
}
__device__ __forceinline__ uint32_t pack2(__nv_bfloat16 a, __nv_bfloat16 b) {
    return (uint32_t)__bfloat16_as_ushort(a) | ((uint32_t)__bfloat16_as_ushort(b) << 16);
}
__device__ __forceinline__ void split4(float4 v, uint2& ph, uint2& pl) {
    __nv_bfloat16 h0, l0, h1, l1, h2, l2, h3, l3;
    split_bf16(v.x, h0, l0); split_bf16(v.y, h1, l1);
    split_bf16(v.z, h2, l2); split_bf16(v.w, h3, l3);
    ph = make_uint2(pack2(h0, h1), pack2(h2, h3));
    pl = make_uint2(pack2(l0, l1), pack2(l2, l3));
}

// ---------------------------------------------------------------------------
// 3 weight matrices (256x256) fp32 -> bf16 hi/lo, one launch via grid.z
// ---------------------------------------------------------------------------
__global__ void convW3_kernel(const float* __restrict__ s0, const float* __restrict__ s1,
                              const float* __restrict__ s2,
                              __nv_bfloat16* __restrict__ h0, __nv_bfloat16* __restrict__ l0,
                              __nv_bfloat16* __restrict__ h1, __nv_bfloat16* __restrict__ l1,
                              __nv_bfloat16* __restrict__ h2, __nv_bfloat16* __restrict__ l2)
{
    const float* src = (blockIdx.z == 0) ? s0 : (blockIdx.z == 1) ? s1 : s2;
    __nv_bfloat16* hi = (blockIdx.z == 0) ? h0 : (blockIdx.z == 1) ? h1 : h2;
    __nv_bfloat16* lo = (blockIdx.z == 0) ? l0 : (blockIdx.z == 1) ? l1 : l2;
    int idx = blockIdx.x * blockDim.x + threadIdx.x;
    float4 v = *reinterpret_cast<const float4*>(src + idx * 4);
    uint2 ph, pl;
    split4(v, ph, pl);
    *reinterpret_cast<uint2*>(hi + idx * 4) = ph;
    *reinterpret_cast<uint2*>(lo + idx * 4) = pl;
}

// ---------------------------------------------------------------------------
// Generic tensor-core GEMM:  D[m,n] += sum_k A[m,k]*B[n,k], bf16x3 split.
// A: normal layout (rows m, k contiguous): bf16 pair (!AF32) or fp32 (AF32).
// B: TRANS source layout [k][n]: bf16 pair (!BF32) or fp32 (BF32).
// fp32 sides: LDG->reg prefetch -> in-reg split -> STS (no staging smem).
// BM=BN=128, BK=32, 256 threads, 2-stage, 2 CTAs/SM. Epilogue: fp32 atomicAdd.
// ---------------------------------------------------------------------------
static constexpr int ABUF = 10240;   // 128 x 80
static constexpr int BBUF = 8704;    // 32 x 272
static constexpr int OFF_B = 4 * ABUF;             // 40960
static constexpr int GEMM_SMEM = OFF_B + 4 * BBUF; // 75776

template<bool AF32, bool BF32>
__global__ void __launch_bounds__(256, 2) gemm_uni_kernel(
    const __nv_bfloat16* __restrict__ Ah, const __nv_bfloat16* __restrict__ Al,
    const float* __restrict__ Af, int aLd,
    const __nv_bfloat16* __restrict__ Bh, const __nv_bfloat16* __restrict__ Bl,
    const float* __restrict__ Bf, int bLd,
    float* __restrict__ out, int outLd, int kPerCta)
{
    extern __shared__ char smem[];
    uint32_t sb = smem_u32(smem);
    const int tid  = threadIdx.x;
    const int wid  = tid >> 5;
    const int lane = tid & 31;
    const int m0 = blockIdx.y * 128;
    const int n0 = blockIdx.x * 128;
    const int kStart = blockIdx.z * kPerCta;
    const int nChunks = kPerCta >> 5;

    const int wm = wid >> 2, wn = wid & 3;
    const int mBase = wm * 64, nBase = wn * 32;
    const int g = lane >> 2, t = lane & 3;
    const int mat = lane >> 3, r = lane & 7;

    const uint32_t aFrag = (uint32_t)(mBase + (mat & 1) * 8 + r) * 80 + (mat >> 1) * 16;
    const uint32_t bFrag = (uint32_t)((mat & 1) * 8 + r) * 272 + (nBase + (mat >> 1) * 8) * 2;

    float acc[4][4][4];
#pragma unroll
    for (int i = 0; i < 4; i++)
#pragma unroll
        for (int j = 0; j < 4; j++)
#pragma unroll
            for (int e = 0; e < 4; e++) acc[i][j][e] = 0.0f;

    float4 afb[4], bfb[4];

    auto ldg_f32 = [&](int kOff) {
        if (AF32) {
#pragma unroll
            for (int i = 0; i < 4; i++) {
                int slot = tid + i * 256;
                afb[i] = *reinterpret_cast<const float4*>(
                    Af + (size_t)(m0 + (slot >> 3)) * aLd + kOff + (slot & 7) * 4);
            }
        }
        if (BF32) {
#pragma unroll
            for (int i = 0; i < 4; i++) {
                int slot = tid + i * 256;
                bfb[i] = *reinterpret_cast<const float4*>(
                    Bf + (size_t)(kOff + (slot >> 5)) * bLd + n0 + (slot & 31) * 4);
            }
        }
    };
    auto sts_f32 = [&](int st) {
        if (AF32) {
#pragma unroll
            for (int i = 0; i < 4; i++) {
                int slot = tid + i * 256;
                int row = slot >> 3, c4 = (slot & 7) * 4;
                uint2 ph, pl;
                split4(afb[i], ph, pl);
                *reinterpret_cast<uint2*>(smem + (st * 2 + 0) * ABUF + row * 80 + c4 * 2) = ph;
                *reinterpret_cast<uint2*>(smem + (st * 2 + 1) * ABUF + row * 80 + c4 * 2) = pl;
            }
        }
        if (BF32) {
#pragma unroll
            for (int i = 0; i < 4; i++) {
                int slot = tid + i * 256;
                int row = slot >> 5, c4 = (slot & 31) * 4;
                uint2 ph, pl;
                split4(bfb[i], ph, pl);
                *reinterpret_cast<uint2*>(smem + OFF_B + (st * 2 + 0) * BBUF + row * 272 + c4 * 2) = ph;
                *reinterpret_cast<uint2*>(smem + OFF_B + (st * 2 + 1) * BBUF + row * 272 + c4 * 2) = pl;
            }
        }
    };
    auto cpa = [&](int st, int kOff) {
        if (!AF32) {
#pragma unroll
            for (int i = 0; i < 4; i++) {
                int idx = tid + i * 256;
                int hl = idx >> 9, rem = idx & 511;
                int row = rem >> 2, ch = rem & 3;
                cp16(sb + (st * 2 + hl) * ABUF + row * 80 + ch * 16,
                     (hl ? Al : Ah) + (size_t)(m0 + row) * aLd + kOff + ch * 8);
            }
        }
        if (!BF32) {
#pragma unroll
            for (int i = 0; i < 4; i++) {
                int idx = tid + i * 256;
                int hl = idx >> 9, rem = idx & 511;
                int row = rem >> 4, ch = rem & 15;
                cp16(sb + OFF_B + (st * 2 + hl) * BBUF + row * 272 + ch * 16,
                     (hl ? Bl : Bh) + (size_t)(kOff + row) * bLd + n0 + ch * 8);
            }
        }
    };

    cpa(0, kStart);
    cp_commit();
    ldg_f32(kStart);
    if (nChunks > 1) { cpa(1, kStart + 32); cp_commit(); }

    for (int ch = 0; ch < nChunks; ch++) {
        const int st = ch & 1;
        sts_f32(st);
        if (ch + 1 < nChunks) cp_wait<1>(); else cp_wait<0>();
        __syncthreads();
        if (ch + 1 < nChunks) ldg_f32(kStart + (ch + 1) * 32);

        const uint32_t aHiB = sb + (st * 2 + 0) * ABUF;
        const uint32_t aLoB = sb + (st * 2 + 1) * ABUF;
        const uint32_t bHiB = sb + OFF_B + (st * 2 + 0) * BBUF;
        const uint32_t bLoB = sb + OFF_B + (st * 2 + 1) * BBUF;
#pragma unroll
        for (int kk = 0; kk < 2; kk++) {
            uint32_t bh[8], bl[8];
#pragma unroll
            for (int p = 0; p < 2; p++) {
                ldm_x4_t(&bh[p * 4], bHiB + bFrag + kk * 4352 + p * 32);
                ldm_x4_t(&bl[p * 4], bLoB + bFrag + kk * 4352 + p * 32);
            }
#pragma unroll
            for (int mt = 0; mt < 4; mt++) {
                uint32_t ah[4], al[4];
                ldm_x4(ah, aHiB + aFrag + mt * 1280 + kk * 32);
                ldm_x4(al, aLoB + aFrag + mt * 1280 + kk * 32);
#pragma unroll
                for (int nt = 0; nt < 4; nt++) {
                    const uint32_t* bhp = &bh[(nt >> 1) * 4 + (nt & 1) * 2];
                    const uint32_t* blp = &bl[(nt >> 1) * 4 + (nt & 1) * 2];
                    mma16816(acc[mt][nt], ah, bhp);
                    mma16816(acc[mt][nt], ah, blp);
                    mma16816(acc[mt][nt], al, bhp);
                }
            }
        }
        __syncthreads();
        if (ch + 2 < nChunks) { cpa(st, kStart + (ch + 2) * 32); cp_commit(); }
    }

#pragma unroll
    for (int mt = 0; mt < 4; mt++) {
#pragma unroll
        for (int nt = 0; nt < 4; nt++) {
            int row = m0 + mBase + mt * 16 + g;
            int col = n0 + nBase + nt * 8 + 2 * t;
            float* p0 = out + (size_t)row * outLd + col;
            float* p1 = out + (size_t)(row + 8) * outLd + col;
            atomicAdd(p0,     acc[mt][nt][0]);
            atomicAdd(p0 + 1, acc[mt][nt][1]);
            atomicAdd(p1,     acc[mt][nt][2]);
            atomicAdd(p1 + 1, acc[mt][nt][3]);
        }
    }
}

// ---------------------------------------------------------------------------
// GEMM1 fused: Klog[j][o] = sum_c key[c][j]*Wk[o][c], then k-softmax over o,
// store Ks [j][o] bf16 hi/lo row-major. A fp32 trans via reg-convert.
// ---------------------------------------------------------------------------
static constexpr int KSM_BBUF  = 20480;                 // 256 x 80
static constexpr int KSM_OFF_A = 4 * KSM_BBUF;          // 81920
static constexpr int KSM_ABUF  = 8704;                  // 32 x 272
static constexpr int KSM_SMEM  = KSM_OFF_A + 4 * KSM_ABUF;   // 116736

__global__ void __launch_bounds__(256, 1) gemm_ksm_kernel(
    const float* __restrict__ keyP,          // key + S0_, ld = S_
    const __nv_bfloat16* __restrict__ Bh, const __nv_bfloat16* __restrict__ Bl,
    __nv_bfloat16* __restrict__ Ks_hi, __nv_bfloat16* __restrict__ Ks_lo)
{
    extern __shared__ char smem[];
    uint32_t sb = smem_u32(smem);
    const int tid  = threadIdx.x;
    const int wid  = tid >> 5;
    const int lane = tid & 31;
    const int j0 = blockIdx.x * 128;

    const int wm = wid >> 2, wn = wid & 3;
    const int mBase = wm * 64, nBase = wn * 64;
    const int g = lane >> 2, t = lane & 3;
    const int mat = lane >> 3, r = lane & 7;

    const uint32_t aFragT = (uint32_t)((mat >> 1) * 8 + r) * 272 + (mBase + (mat & 1) * 8) * 2;
    const uint32_t bFrag = (uint32_t)(nBase + (mat >> 1) * 8 + r) * 80 + (mat & 1) * 16;

    float acc[4][8][4];
#pragma unroll
    for (int i = 0; i < 4; i++)
#pragma unroll
        for (int j = 0; j < 8; j++)
#pragma unroll
            for (int e = 0; e < 4; e++) acc[i][j][e] = 0.0f;

    float4 afb[4];
    auto ldg_a = [&](int kOff) {
#pragma unroll
        for (int i = 0; i < 4; i++) {
            int slot = tid + i * 256;
            afb[i] = *reinterpret_cast<const float4*>(
                keyP + (size_t)(kOff + (slot >> 5)) * S_ + j0 + (slot & 31) * 4);
        }
    };
    auto sts_a = [&](int st) {
#pragma unroll
        for (int i = 0; i < 4; i++) {
            int slot = tid + i * 256;
            int row = slot >> 5, c4 = (slot & 31) * 4;
            uint2 ph, pl;
            split4(afb[i], ph, pl);
            *reinterpret_cast<uint2*>(smem + KSM_OFF_A + (st * 2 + 0) * KSM_ABUF + row * 272 + c4 * 2) = ph;
            *reinterpret_cast<uint2*>(smem + KSM_OFF_A + (st * 2 + 1) * KSM_ABUF + row * 272 + c4 * 2) = pl;
        }
    };
    auto cpb = [&](int st, int kOff) {
#pragma unroll
        for (int i = 0; i < 8; i++) {
            int idx = tid + i * 256;
            int hl = idx >> 10, rem = idx & 1023;
            int row = rem >> 2, ch = rem & 3;
            cp16(sb + (st * 2 + hl) * KSM_BBUF + row * 80 + ch * 16,
                 (hl ? Bl : Bh) + (size_t)row * C_ + kOff + ch * 8);
        }
    };

    cpb(0, 0);
    cp_commit();
    ldg_a(0);
    cpb(1, 32);
    cp_commit();

    const int nChunks = 8;
    for (int ch = 0; ch < nChunks; ch++) {
        const int st = ch & 1;
        sts_a(st);
        if (ch + 1 < nChunks) cp_wait<1>(); else cp_wait<0>();
        __syncthreads();
        if (ch + 1 < nChunks) ldg_a((ch + 1) * 32);

        const uint32_t aHiB = sb + KSM_OFF_A + (st * 2 + 0) * KSM_ABUF;
        const uint32_t aLoB = sb + KSM_OFF_A + (st * 2 + 1) * KSM_ABUF;
        const uint32_t bHiB = sb + (st * 2 + 0) * KSM_BBUF;
        const uint32_t bLoB = sb + (st * 2 + 1) * KSM_BBUF;
#pragma unroll
        for (int kk = 0; kk < 2; kk++) {
            uint32_t ah[4][4], al[4][4];
#pragma unroll
            for (int mt = 0; mt < 4; mt++) {
                ldm_x4_t(ah[mt], aHiB + aFragT + kk * 4352 + mt * 32);
                ldm_x4_t(al[mt], aLoB + aFragT + kk * 4352 + mt * 32);
            }
#pragma unroll
            for (int ph = 0; ph < 2; ph++) {
                uint32_t bh8[8], bl8[8];
#pragma unroll
                for (int pl = 0; pl < 2; pl++) {
                    ldm_x4(&bh8[pl * 4], bHiB + bFrag + (ph * 2 + pl) * 1280 + kk * 32);
                    ldm_x4(&bl8[pl * 4], bLoB + bFrag + (ph * 2 + pl) * 1280 + kk * 32);
                }
#pragma unroll
                for (int mt = 0; mt < 4; mt++) {
#pragma unroll
                    for (int l = 0; l < 4; l++) {
                        const uint32_t* bhp = &bh8[(l >> 1) * 4 + (l & 1) * 2];
                        const uint32_t* blp = &bl8[(l >> 1) * 4 + (l & 1) * 2];
                        int nt = ph * 4 + l;
                        mma16816(acc[mt][nt], ah[mt], bhp);
                        mma16816(acc[mt][nt], ah[mt], blp);
                        mma16816(acc[mt][nt], al[mt], bhp);
                    }
                }
            }
        }
        __syncthreads();
        if (ch + 2 < nChunks) { cpb(st, (ch + 2) * 32); cp_commit(); }
    }

    // fused epilogue: row softmax over 256 cols
    float* redA = reinterpret_cast<float*>(smem);
    float* redB = redA + 512;

    float rmax[4][2];
#pragma unroll
    for (int mt = 0; mt < 4; mt++) {
#pragma unroll
        for (int h = 0; h < 2; h++) {
            float m = -1e30f;
#pragma unroll
            for (int nt = 0; nt < 8; nt++) {
                m = fmaxf(m, acc[mt][nt][h * 2 + 0]);
                m = fmaxf(m, acc[mt][nt][h * 2 + 1]);
            }
            m = fmaxf(m, __shfl_xor_sync(0xffffffffu, m, 1));
            m = fmaxf(m, __shfl_xor_sync(0xffffffffu, m, 2));
            if (t == 0) redA[(mBase + mt * 16 + h * 8 + g) * 4 + wn] = m;
        }
    }
    __syncthreads();
#pragma unroll
    for (int mt = 0; mt < 4; mt++)
#pragma unroll
        for (int h = 0; h < 2; h++) {
            int row = mBase + mt * 16 + h * 8 + g;
            float m = fmaxf(fmaxf(redA[row * 4], redA[row * 4 + 1]),
                            fmaxf(redA[row * 4 + 2], redA[row * 4 + 3]));
            rmax[mt][h] = m * INV_TEMP;
        }

    float rinv[4][2];
#pragma unroll
    for (int mt = 0; mt < 4; mt++) {
#pragma unroll
        for (int h = 0; h < 2; h++) {
            float s = 0.0f;
#pragma unroll
            for (int nt = 0; nt < 8; nt++) {
#pragma unroll
                for (int e2 = 0; e2 < 2; e2++) {
                    float w = __expf(acc[mt][nt][h * 2 + e2] * INV_TEMP - rmax[mt][h]);
                    acc[mt][nt][h * 2 + e2] = w;
                    s += w;
                }
            }
            s += __shfl_xor_sync(0xffffffffu, s, 1);
            s += __shfl_xor_sync(0xffffffffu, s, 2);
            if (t == 0) redB[(mBase + mt * 16 + h * 8 + g) * 4 + wn] = s;
        }
    }
    __syncthreads();
#pragma unroll
    for (int mt = 0; mt < 4; mt++)
#pragma unroll
        for (int h = 0; h < 2; h++) {
            int row = mBase + mt * 16 + h * 8 + g;
            float s = redB[row * 4] + redB[row * 4 + 1] + redB[row * 4 + 2] + redB[row * 4 + 3];
            rinv[mt][h] = 1.0f / s;
        }

#pragma unroll
    for (int mt = 0; mt < 4; mt++) {
#pragma unroll
        for (int h = 0; h < 2; h++) {
            int j = j0 + mBase + mt * 16 + h * 8 + g;
#pragma unroll
            for (int nt = 0; nt < 8; nt++) {
                int col = nBase + nt * 8 + 2 * t;
                float w0 = acc[mt][nt][h * 2 + 0] * rinv[mt][h];
                float w1 = acc[mt][nt][h * 2 + 1] * rinv[mt][h];
                __nv_bfloat16 h0, l0, h1, l1;
                split_bf16(w0, h0, l0);
                split_bf16(w1, h1, l1);
                size_t o = (size_t)j * C_ + col;
                *reinterpret_cast<uint32_t*>(Ks_hi + o) = pack2(h0, h1);
                *reinterpret_cast<uint32_t*>(Ks_lo + o) = pack2(l0, l1);
            }
        }
    }
}

// ---------------------------------------------------------------------------
// q softmax over hw (rows of 4096), 512 threads: fp32 -> bf16 hi/lo
// ---------------------------------------------------------------------------
__global__ void __launch_bounds__(512) qsoftmax_kernel(
    const float* __restrict__ Qlog,
    __nv_bfloat16* __restrict__ Qs_hi, __nv_bfloat16* __restrict__ Qs_lo)
{
    constexpr int NT = 512, NE = 8;
    const float* row = Qlog + (size_t)blockIdx.x * HW_;
    __shared__ float sred[32];
    const int tid = threadIdx.x;
    const int lane = tid & 31;
    const int wid = tid >> 5;

    float v[NE];
    float m = -1e30f;
#pragma unroll
    for (int e = 0; e < NE; e++) {
        v[e] = row[tid + e * NT] * INV_TEMP;
        m = fmaxf(m, v[e]);
    }
#pragma unroll
    for (int o = 16; o > 0; o >>= 1) m = fmaxf(m, __shfl_xor_sync(0xffffffffu, m, o));
    if (lane == 0) sred[wid] = m;
    __syncthreads();
    if (wid == 0) {
        float tv = (lane < 16) ? sred[lane] : -1e30f;
#pragma unroll
        for (int o = 16; o > 0; o >>= 1) tv = fmaxf(tv, __shfl_xor_sync(0xffffffffu, tv, o));
        if (lane == 0) sred[0] = tv;
    }
    __syncthreads();
    m = sred[0];
    __syncthreads();

    float sum = 0.0f;
#pragma unroll
    for (int e = 0; e < NE; e++) {
        v[e] = __expf(v[e] - m);
        sum += v[e];
    }
#pragma unroll
    for (int o = 16; o > 0; o >>= 1) sum += __shfl_xor_sync(0xffffffffu, sum, o);
    if (lane == 0) sred[wid] = sum;
    __syncthreads();
    if (wid == 0) {
        float tv = (lane < 16) ? sred[lane] : 0.0f;
#pragma unroll
        for (int o = 16; o > 0; o >>= 1) tv += __shfl_xor_sync(0xffffffffu, tv, o);
        if (lane == 0) sred[0] = tv;
    }
    __syncthreads();
    float inv = 1.0f / sred[0];
    size_t base = (size_t)blockIdx.x * HW_;
#pragma unroll
    for (int e = 0; e < NE; e++) {
        float w = v[e] * inv;
        __nv_bfloat16 h, l;
        split_bf16(w, h, l);
        Qs_hi[base + tid + e * NT] = h;
        Qs_lo[base + tid + e * NT] = l;
    }
}

__global__ void zero_kernel(float* __restrict__ p, int n)
{
    int i = blockIdx.x * blockDim.x + threadIdx.x;
    if (i < n) p[i] = 0.0f;
}

// ---------------------------------------------------------------------------
// Launch
// ---------------------------------------------------------------------------
extern "C" void kernel_launch(void* const* d_in, const int* in_sizes, int n_in,
                              void* d_out, int out_size)
{
    (void)in_sizes; (void)n_in; (void)out_size;
    const float* query = (const float*)d_in[0]; // (C, HW)
    const float* key   = (const float*)d_in[1]; // (C, S)
    const float* value = (const float*)d_in[2]; // (C, S)
    const float* Wq    = (const float*)d_in[3]; // (C, C)
    const float* Wk    = (const float*)d_in[4];
    const float* Wv    = (const float*)d_in[5];
    float* out = (float*)d_out;                 // (C, HW)

    static bool s_init = false;
    static cudaStream_t s1, s2;
    static cudaEvent_t evF, evJ1, evJ2;
    if (!s_init) {
        cudaStreamCreateWithFlags(&s1, cudaStreamNonBlocking);
        cudaStreamCreateWithFlags(&s2, cudaStreamNonBlocking);
        cudaEventCreateWithFlags(&evF,  cudaEventDisableTiming);
        cudaEventCreateWithFlags(&evJ1, cudaEventDisableTiming);
        cudaEventCreateWithFlags(&evJ2, cudaEventDisableTiming);
        cudaFuncSetAttribute(gemm_uni_kernel<false, true>, cudaFuncAttributeMaxDynamicSharedMemorySize, GEMM_SMEM);
        cudaFuncSetAttribute(gemm_uni_kernel<true, false>, cudaFuncAttributeMaxDynamicSharedMemorySize, GEMM_SMEM);
        cudaFuncSetAttribute(gemm_ksm_kernel, cudaFuncAttributeMaxDynamicSharedMemorySize, KSM_SMEM);
        s_init = true;
    }

    __nv_bfloat16 *Ks_hi, *Ks_lo, *Qs_hi, *Qs_lo;
    __nv_bfloat16 *Wq_hi, *Wq_lo, *Wk_hi, *Wk_lo, *Wv_hi, *Wv_lo;
    float *Qlog, *T2, *G;
    cudaGetSymbolAddress((void**)&Ks_hi, g_Ks_hi);
    cudaGetSymbolAddress((void**)&Ks_lo, g_Ks_lo);
    cudaGetSymbolAddress((void**)&Qs_hi, g_Qs_hi);
    cudaGetSymbolAddress((void**)&Qs_lo, g_Qs_lo);
    cudaGetSymbolAddress((void**)&Wq_hi, g_Wq_hi);
    cudaGetSymbolAddress((void**)&Wq_lo, g_Wq_lo);
    cudaGetSymbolAddress((void**)&Wk_hi, g_Wk_hi);
    cudaGetSymbolAddress((void**)&Wk_lo, g_Wk_lo);
    cudaGetSymbolAddress((void**)&Wv_hi, g_Wv_hi);
    cudaGetSymbolAddress((void**)&Wv_lo, g_Wv_lo);
    cudaGetSymbolAddress((void**)&Qlog,  g_Qlog);
    cudaGetSymbolAddress((void**)&T2,    g_T2);
    cudaGetSymbolAddress((void**)&G,     g_G);

    // main: weight conversion, then fork
    convW3_kernel<<<dim3(64, 1, 3), 256>>>(Wq, Wk, Wv, Wq_hi, Wq_lo, Wk_hi, Wk_lo, Wv_hi, Wv_lo);
    cudaEventRecord(evF, 0);
    cudaStreamWaitEvent(s1, evF, 0);
    cudaStreamWaitEvent(s2, evF, 0);

    // s1: Ks path (GEMM1 + fused k-softmax)
    gemm_ksm_kernel<<<SA_ / 128, 256, KSM_SMEM, s1>>>(key + S0_, Wk_hi, Wk_lo, Ks_hi, Ks_lo);
    cudaEventRecord(evJ1, s1);

    // s2: Qs path (split-K 4 -> 256 CTAs, 2 CTAs/SM)
    zero_kernel<<<(C_ * HW_ + 255) / 256, 256, 0, s2>>>(Qlog, C_ * HW_);
    gemm_uni_kernel<false, true><<<dim3(HW_ / 128, C_ / 128, 4), 256, GEMM_SMEM, s2>>>(
        Wq_hi, Wq_lo, nullptr, C_, nullptr, nullptr, query, HW_, Qlog, HW_, C_ / 4);
    qsoftmax_kernel<<<C_, 512, 0, s2>>>(Qlog, Qs_hi, Qs_lo);
    cudaEventRecord(evJ2, s2);

    // main: zero accumulators (overlaps both branches)
    zero_kernel<<<(C_ * C_ + 255) / 256, 256>>>(T2, C_ * C_);
    zero_kernel<<<(C_ * C_ + 255) / 256, 256>>>(G, C_ * C_);
    zero_kernel<<<(C_ * HW_ + 255) / 256, 256>>>(out, C_ * HW_);

    // join Ks path -> GEMM3 (T2, split-K 64 -> 256 CTAs), GEMM4 (G)
    cudaStreamWaitEvent(0, evJ1, 0);
    gemm_uni_kernel<true, false><<<dim3(C_ / 128, C_ / 128, 64), 256, GEMM_SMEM>>>(
        nullptr, nullptr, value + S0_, S_, Ks_hi, Ks_lo, nullptr, C_, T2, C_, SA_ / 64);
    gemm_uni_kernel<false, true><<<dim3(C_ / 128, C_ / 128, 8), 256, GEMM_SMEM>>>(
        Wv_hi, Wv_lo, nullptr, C_, nullptr, nullptr, T2, C_, G, C_, C_ / 8);

    // join Qs path -> GEMM5 (split-K 4 -> 256 CTAs)
    cudaStreamWaitEvent(0, evJ2, 0);
    gemm_uni_kernel<true, false><<<dim3(HW_ / 128, C_ / 128, 4), 256, GEMM_SMEM>>>(
        nullptr, nullptr, G, C_, Qs_hi, Qs_lo, nullptr, HW_, out, HW_, C_ / 4);
}

// round 9
// speedup vs baseline: 1.5085x; 1.0027x over previous
#include <cuda_runtime.h>
#include <cuda_bf16.h>
#include <cstdint>

// ---------------------------------------------------------------------------
// Problem constants (B=1)
// ---------------------------------------------------------------------------
static constexpr int C_   = 256;
static constexpr int HW_  = 4096;     // 64*64
static constexpr int S_   = 32768;    // 8*64*64
static constexpr int SA_  = 20480;    // 5*64*64 active (last 5 frames)
static constexpr int S0_  = S_ - SA_; // 12288
static constexpr float INV_TEMP = 10.0f;

// ---------------------------------------------------------------------------
// Device scratch
// ---------------------------------------------------------------------------
__device__ __align__(16) __nv_bfloat16 g_Ks_hi [SA_ * C_];   // [j][o]  (k-softmaxed)
__device__ __align__(16) __nv_bfloat16 g_Ks_lo [SA_ * C_];
__device__ __align__(16) __nv_bfloat16 g_Qs_hi [C_ * HW_];   // [o][hw] (q-softmaxed)
__device__ __align__(16) __nv_bfloat16 g_Qs_lo [C_ * HW_];
__device__ __align__(16) __nv_bfloat16 g_Wq_hi[C_ * C_], g_Wq_lo[C_ * C_];
__device__ __align__(16) __nv_bfloat16 g_Wk_hi[C_ * C_], g_Wk_lo[C_ * C_];
__device__ __align__(16) __nv_bfloat16 g_Wv_hi[C_ * C_], g_Wv_lo[C_ * C_];
__device__ __align__(16) float g_Qlog[C_ * HW_];   // q logits (split-K accumulator)
__device__ __align__(16) float g_T2  [C_ * C_];    // split-K accumulator [a][o]
__device__ __align__(16) float g_G   [C_ * C_];    // split-K accumulator [c][o]

// ---------------------------------------------------------------------------
// PTX helpers (compute_100-safe)
// ---------------------------------------------------------------------------
__device__ __forceinline__ uint32_t smem_u32(const void* p) {
    uint32_t a;
    asm("{ .reg .u64 t; cvta.to.shared.u64 t, %1; cvt.u32.u64 %0, t; }" : "=r"(a) : "l"(p));
    return a;
}
__device__ __forceinline__ void cp16(uint32_t dst, const void* src) {
    asm volatile("cp.async.cg.shared.global [%0], [%1], 16;" :: "r"(dst), "l"(src));
}
__device__ __forceinline__ void cp_commit() {
    asm volatile("cp.async.commit_group;" ::: "memory");
}
template<int N>
__device__ __forceinline__ void cp_wait() {
    asm volatile("cp.async.wait_group %0;" :: "n"(N) : "memory");
}
__device__ __forceinline__ void ldm_x4(uint32_t* r, uint32_t addr) {
    asm volatile("ldmatrix.sync.aligned.m8n8.x4.shared.b16 {%0,%1,%2,%3}, [%4];"
                 : "=r"(r[0]), "=r"(r[1]), "=r"(r[2]), "=r"(r[3]) : "r"(addr));
}
__device__ __forceinline__ void ldm_x4_t(uint32_t* r, uint32_t addr) {
    asm volatile("ldmatrix.sync.aligned.m8n8.x4.trans.shared.b16 {%0,%1,%2,%3}, [%4];"
                 : "=r"(r[0]), "=r"(r[1]), "=r"(r[2]), "=r"(r[3]) : "r"(addr));
}
__device__ __forceinline__ void mma16816(float* c, const uint32_t* a, const uint32_t* b) {
    asm volatile(
        "mma.sync.aligned.m16n8k16.row.col.f32.bf16.bf16.f32 "
        "{%0,%1,%2,%3}, {%4,%5,%6,%7}, {%8,%9}, {%0,%1,%2,%3};"
        : "+f"(c[0]), "+f"(c[1]), "+f"(c[2]), "+f"(c[3])
        : "r"(a[0]), "r"(a[1]), "r"(a[2]), "r"(a[3]), "r"(b[0]), "r"(b[1]));
}
__device__ __forceinline__ void split_bf16(float v, __nv_bfloat16& h, __nv_bfloat16& l) {
    h = __float2bfloat16(v);
    l = __float2bfloat16(v - __bfloat162float(h));
}
__device__ __forceinline__ uint32_t pack2(__nv_bfloat16 a, __nv_bfloat16 b) {
    return (uint32_t)__bfloat16_as_ushort(a) | ((uint32_t)__bfloat16_as_ushort(b) << 16);
}
__device__ __forceinline__ void split4(float4 v, uint2& ph, uint2& pl) {
    __nv_bfloat16 h0, l0, h1, l1, h2, l2, h3, l3;
    split_bf16(v.x, h0, l0); split_bf16(v.y, h1, l1);
    split_bf16(v.z, h2, l2); split_bf16(v.w, h3, l3);
    ph = make_uint2(pack2(h0, h1), pack2(h2, h3));
    pl = make_uint2(pack2(l0, l1), pack2(l2, l3));
}

// ---------------------------------------------------------------------------
// 3 weight matrices (256x256) fp32 -> bf16 hi/lo, one launch via grid.z
// ---------------------------------------------------------------------------
__global__ void convW3_kernel(const float* __restrict__ s0, const float* __restrict__ s1,
                              const float* __restrict__ s2,
                              __nv_bfloat16* __restrict__ h0, __nv_bfloat16* __restrict__ l0,
                              __nv_bfloat16* __restrict__ h1, __nv_bfloat16* __restrict__ l1,
                              __nv_bfloat16* __restrict__ h2, __nv_bfloat16* __restrict__ l2)
{
    const float* src = (blockIdx.z == 0) ? s0 : (blockIdx.z == 1) ? s1 : s2;
    __nv_bfloat16* hi = (blockIdx.z == 0) ? h0 : (blockIdx.z == 1) ? h1 : h2;
    __nv_bfloat16* lo = (blockIdx.z == 0) ? l0 : (blockIdx.z == 1) ? l1 : l2;
    int idx = blockIdx.x * blockDim.x + threadIdx.x;
    float4 v = *reinterpret_cast<const float4*>(src + idx * 4);
    uint2 ph, pl;
    split4(v, ph, pl);
    *reinterpret_cast<uint2*>(hi + idx * 4) = ph;
    *reinterpret_cast<uint2*>(lo + idx * 4) = pl;
}

// ---------------------------------------------------------------------------
// Generic tensor-core GEMM:  D[m,n] += sum_k A[m,k]*B[n,k], bf16x3 split.
// A: normal layout (rows m, k contiguous): bf16 pair (!AF32) or fp32 (AF32).
// B: TRANS source layout [k][n]: bf16 pair (!BF32) or fp32 (BF32).
// fp32 sides: LDG->reg prefetch -> in-reg split -> STS (no staging smem).
// BM=BN=128, BK=32, 256 threads, 2-stage, 2 CTAs/SM. Epilogue: fp32 atomicAdd.
// MMA issue order: term-outer (hh,hl,lh) x nt-inner -> acc reuse distance 4.
// ---------------------------------------------------------------------------
static constexpr int ABUF = 10240;   // 128 x 80
static constexpr int BBUF = 8704;    // 32 x 272
static constexpr int OFF_B = 4 * ABUF;             // 40960
static constexpr int GEMM_SMEM = OFF_B + 4 * BBUF; // 75776

template<bool AF32, bool BF32>
__global__ void __launch_bounds__(256, 2) gemm_uni_kernel(
    const __nv_bfloat16* __restrict__ Ah, const __nv_bfloat16* __restrict__ Al,
    const float* __restrict__ Af, int aLd,
    const __nv_bfloat16* __restrict__ Bh, const __nv_bfloat16* __restrict__ Bl,
    const float* __restrict__ Bf, int bLd,
    float* __restrict__ out, int outLd, int kPerCta)
{
    extern __shared__ char smem[];
    uint32_t sb = smem_u32(smem);
    const int tid  = threadIdx.x;
    const int wid  = tid >> 5;
    const int lane = tid & 31;
    const int m0 = blockIdx.y * 128;
    const int n0 = blockIdx.x * 128;
    const int kStart = blockIdx.z * kPerCta;
    const int nChunks = kPerCta >> 5;

    const int wm = wid >> 2, wn = wid & 3;
    const int mBase = wm * 64, nBase = wn * 32;
    const int g = lane >> 2, t = lane & 3;
    const int mat = lane >> 3, r = lane & 7;

    const uint32_t aFrag = (uint32_t)(mBase + (mat & 1) * 8 + r) * 80 + (mat >> 1) * 16;
    const uint32_t bFrag = (uint32_t)((mat & 1) * 8 + r) * 272 + (nBase + (mat >> 1) * 8) * 2;

    float acc[4][4][4];
#pragma unroll
    for (int i = 0; i < 4; i++)
#pragma unroll
        for (int j = 0; j < 4; j++)
#pragma unroll
            for (int e = 0; e < 4; e++) acc[i][j][e] = 0.0f;

    float4 afb[4], bfb[4];

    auto ldg_f32 = [&](int kOff) {
        if (AF32) {
#pragma unroll
            for (int i = 0; i < 4; i++) {
                int slot = tid + i * 256;
                afb[i] = *reinterpret_cast<const float4*>(
                    Af + (size_t)(m0 + (slot >> 3)) * aLd + kOff + (slot & 7) * 4);
            }
        }
        if (BF32) {
#pragma unroll
            for (int i = 0; i < 4; i++) {
                int slot = tid + i * 256;
                bfb[i] = *reinterpret_cast<const float4*>(
                    Bf + (size_t)(kOff + (slot >> 5)) * bLd + n0 + (slot & 31) * 4);
            }
        }
    };
    auto sts_f32 = [&](int st) {
        if (AF32) {
#pragma unroll
            for (int i = 0; i < 4; i++) {
                int slot = tid + i * 256;
                int row = slot >> 3, c4 = (slot & 7) * 4;
                uint2 ph, pl;
                split4(afb[i], ph, pl);
                *reinterpret_cast<uint2*>(smem + (st * 2 + 0) * ABUF + row * 80 + c4 * 2) = ph;
                *reinterpret_cast<uint2*>(smem + (st * 2 + 1) * ABUF + row * 80 + c4 * 2) = pl;
            }
        }
        if (BF32) {
#pragma unroll
            for (int i = 0; i < 4; i++) {
                int slot = tid + i * 256;
                int row = slot >> 5, c4 = (slot & 31) * 4;
                uint2 ph, pl;
                split4(bfb[i], ph, pl);
                *reinterpret_cast<uint2*>(smem + OFF_B + (st * 2 + 0) * BBUF + row * 272 + c4 * 2) = ph;
                *reinterpret_cast<uint2*>(smem + OFF_B + (st * 2 + 1) * BBUF + row * 272 + c4 * 2) = pl;
            }
        }
    };
    auto cpa = [&](int st, int kOff) {
        if (!AF32) {
#pragma unroll
            for (int i = 0; i < 4; i++) {
                int idx = tid + i * 256;
                int hl = idx >> 9, rem = idx & 511;
                int row = rem >> 2, ch = rem & 3;
                cp16(sb + (st * 2 + hl) * ABUF + row * 80 + ch * 16,
                     (hl ? Al : Ah) + (size_t)(m0 + row) * aLd + kOff + ch * 8);
            }
        }
        if (!BF32) {
#pragma unroll
            for (int i = 0; i < 4; i++) {
                int idx = tid + i * 256;
                int hl = idx >> 9, rem = idx & 511;
                int row = rem >> 4, ch = rem & 15;
                cp16(sb + OFF_B + (st * 2 + hl) * BBUF + row * 272 + ch * 16,
                     (hl ? Bl : Bh) + (size_t)(kOff + row) * bLd + n0 + ch * 8);
            }
        }
    };

    cpa(0, kStart);
    cp_commit();
    ldg_f32(kStart);
    if (nChunks > 1) { cpa(1, kStart + 32); cp_commit(); }

    for (int ch = 0; ch < nChunks; ch++) {
        const int st = ch & 1;
        sts_f32(st);
        if (ch + 1 < nChunks) cp_wait<1>(); else cp_wait<0>();
        __syncthreads();
        if (ch + 1 < nChunks) ldg_f32(kStart + (ch + 1) * 32);

        const uint32_t aHiB = sb + (st * 2 + 0) * ABUF;
        const uint32_t aLoB = sb + (st * 2 + 1) * ABUF;
        const uint32_t bHiB = sb + OFF_B + (st * 2 + 0) * BBUF;
        const uint32_t bLoB = sb + OFF_B + (st * 2 + 1) * BBUF;
#pragma unroll
        for (int kk = 0; kk < 2; kk++) {
            uint32_t bh[8], bl[8];
#pragma unroll
            for (int p = 0; p < 2; p++) {
                ldm_x4_t(&bh[p * 4], bHiB + bFrag + kk * 4352 + p * 32);
                ldm_x4_t(&bl[p * 4], bLoB + bFrag + kk * 4352 + p * 32);
            }
#pragma unroll
            for (int mt = 0; mt < 4; mt++) {
                uint32_t ah[4], al[4];
                ldm_x4(ah, aHiB + aFrag + mt * 1280 + kk * 32);
                ldm_x4(al, aLoB + aFrag + mt * 1280 + kk * 32);
                // term-outer ordering: acc reuse distance = 4 independent MMAs
#pragma unroll
                for (int nt = 0; nt < 4; nt++)
                    mma16816(acc[mt][nt], ah, &bh[(nt >> 1) * 4 + (nt & 1) * 2]);
#pragma unroll
                for (int nt = 0; nt < 4; nt++)
                    mma16816(acc[mt][nt], ah, &bl[(nt >> 1) * 4 + (nt & 1) * 2]);
#pragma unroll
                for (int nt = 0; nt < 4; nt++)
                    mma16816(acc[mt][nt], al, &bh[(nt >> 1) * 4 + (nt & 1) * 2]);
            }
        }
        __syncthreads();
        if (ch + 2 < nChunks) { cpa(st, kStart + (ch + 2) * 32); cp_commit(); }
    }

#pragma unroll
    for (int mt = 0; mt < 4; mt++) {
#pragma unroll
        for (int nt = 0; nt < 4; nt++) {
            int row = m0 + mBase + mt * 16 + g;
            int col = n0 + nBase + nt * 8 + 2 * t;
            float* p0 = out + (size_t)row * outLd + col;
            float* p1 = out + (size_t)(row + 8) * outLd + col;
            atomicAdd(p0,     acc[mt][nt][0]);
            atomicAdd(p0 + 1, acc[mt][nt][1]);
            atomicAdd(p1,     acc[mt][nt][2]);
            atomicAdd(p1 + 1, acc[mt][nt][3]);
        }
    }
}

// ---------------------------------------------------------------------------
// GEMM1 fused: Klog[j][o] = sum_c key[c][j]*Wk[o][c], then k-softmax over o,
// store Ks [j][o] bf16 hi/lo row-major. A fp32 trans via reg-convert.
// ---------------------------------------------------------------------------
static constexpr int KSM_BBUF  = 20480;                 // 256 x 80
static constexpr int KSM_OFF_A = 4 * KSM_BBUF;          // 81920
static constexpr int KSM_ABUF  = 8704;                  // 32 x 272
static constexpr int KSM_SMEM  = KSM_OFF_A + 4 * KSM_ABUF;   // 116736

__global__ void __launch_bounds__(256, 1) gemm_ksm_kernel(
    const float* __restrict__ keyP,          // key + S0_, ld = S_
    const __nv_bfloat16* __restrict__ Bh, const __nv_bfloat16* __restrict__ Bl,
    __nv_bfloat16* __restrict__ Ks_hi, __nv_bfloat16* __restrict__ Ks_lo)
{
    extern __shared__ char smem[];
    uint32_t sb = smem_u32(smem);
    const int tid  = threadIdx.x;
    const int wid  = tid >> 5;
    const int lane = tid & 31;
    const int j0 = blockIdx.x * 128;

    const int wm = wid >> 2, wn = wid & 3;
    const int mBase = wm * 64, nBase = wn * 64;
    const int g = lane >> 2, t = lane & 3;
    const int mat = lane >> 3, r = lane & 7;

    const uint32_t aFragT = (uint32_t)((mat >> 1) * 8 + r) * 272 + (mBase + (mat & 1) * 8) * 2;
    const uint32_t bFrag = (uint32_t)(nBase + (mat >> 1) * 8 + r) * 80 + (mat & 1) * 16;

    float acc[4][8][4];
#pragma unroll
    for (int i = 0; i < 4; i++)
#pragma unroll
        for (int j = 0; j < 8; j++)
#pragma unroll
            for (int e = 0; e < 4; e++) acc[i][j][e] = 0.0f;

    float4 afb[4];
    auto ldg_a = [&](int kOff) {
#pragma unroll
        for (int i = 0; i < 4; i++) {
            int slot = tid + i * 256;
            afb[i] = *reinterpret_cast<const float4*>(
                keyP + (size_t)(kOff + (slot >> 5)) * S_ + j0 + (slot & 31) * 4);
        }
    };
    auto sts_a = [&](int st) {
#pragma unroll
        for (int i = 0; i < 4; i++) {
            int slot = tid + i * 256;
            int row = slot >> 5, c4 = (slot & 31) * 4;
            uint2 ph, pl;
            split4(afb[i], ph, pl);
            *reinterpret_cast<uint2*>(smem + KSM_OFF_A + (st * 2 + 0) * KSM_ABUF + row * 272 + c4 * 2) = ph;
            *reinterpret_cast<uint2*>(smem + KSM_OFF_A + (st * 2 + 1) * KSM_ABUF + row * 272 + c4 * 2) = pl;
        }
    };
    auto cpb = [&](int st, int kOff) {
#pragma unroll
        for (int i = 0; i < 8; i++) {
            int idx = tid + i * 256;
            int hl = idx >> 10, rem = idx & 1023;
            int row = rem >> 2, ch = rem & 3;
            cp16(sb + (st * 2 + hl) * KSM_BBUF + row * 80 + ch * 16,
                 (hl ? Bl : Bh) + (size_t)row * C_ + kOff + ch * 8);
        }
    };

    cpb(0, 0);
    cp_commit();
    ldg_a(0);
    cpb(1, 32);
    cp_commit();

    const int nChunks = 8;
    for (int ch = 0; ch < nChunks; ch++) {
        const int st = ch & 1;
        sts_a(st);
        if (ch + 1 < nChunks) cp_wait<1>(); else cp_wait<0>();
        __syncthreads();
        if (ch + 1 < nChunks) ldg_a((ch + 1) * 32);

        const uint32_t aHiB = sb + KSM_OFF_A + (st * 2 + 0) * KSM_ABUF;
        const uint32_t aLoB = sb + KSM_OFF_A + (st * 2 + 1) * KSM_ABUF;
        const uint32_t bHiB = sb + (st * 2 + 0) * KSM_BBUF;
        const uint32_t bLoB = sb + (st * 2 + 1) * KSM_BBUF;
#pragma unroll
        for (int kk = 0; kk < 2; kk++) {
            uint32_t ah[4][4], al[4][4];
#pragma unroll
            for (int mt = 0; mt < 4; mt++) {
                ldm_x4_t(ah[mt], aHiB + aFragT + kk * 4352 + mt * 32);
                ldm_x4_t(al[mt], aLoB + aFragT + kk * 4352 + mt * 32);
            }
#pragma unroll
            for (int ph = 0; ph < 2; ph++) {
                uint32_t bh8[8], bl8[8];
#pragma unroll
                for (int pl = 0; pl < 2; pl++) {
                    ldm_x4(&bh8[pl * 4], bHiB + bFrag + (ph * 2 + pl) * 1280 + kk * 32);
                    ldm_x4(&bl8[pl * 4], bLoB + bFrag + (ph * 2 + pl) * 1280 + kk * 32);
                }
                // term-outer ordering: acc reuse distance = 4
#pragma unroll
                for (int mt = 0; mt < 4; mt++) {
#pragma unroll
                    for (int l = 0; l < 4; l++)
                        mma16816(acc[mt][ph * 4 + l], ah[mt], &bh8[(l >> 1) * 4 + (l & 1) * 2]);
#pragma unroll
                    for (int l = 0; l < 4; l++)
                        mma16816(acc[mt][ph * 4 + l], ah[mt], &bl8[(l >> 1) * 4 + (l & 1) * 2]);
#pragma unroll
                    for (int l = 0; l < 4; l++)
                        mma16816(acc[mt][ph * 4 + l], al[mt], &bh8[(l >> 1) * 4 + (l & 1) * 2]);
                }
            }
        }
        __syncthreads();
        if (ch + 2 < nChunks) { cpb(st, (ch + 2) * 32); cp_commit(); }
    }

    // fused epilogue: row softmax over 256 cols
    float* redA = reinterpret_cast<float*>(smem);
    float* redB = redA + 512;

    float rmax[4][2];
#pragma unroll
    for (int mt = 0; mt < 4; mt++) {
#pragma unroll
        for (int h = 0; h < 2; h++) {
            float m = -1e30f;
#pragma unroll
            for (int nt = 0; nt < 8; nt++) {
                m = fmaxf(m, acc[mt][nt][h * 2 + 0]);
                m = fmaxf(m, acc[mt][nt][h * 2 + 1]);
            }
            m = fmaxf(m, __shfl_xor_sync(0xffffffffu, m, 1));
            m = fmaxf(m, __shfl_xor_sync(0xffffffffu, m, 2));
            if (t == 0) redA[(mBase + mt * 16 + h * 8 + g) * 4 + wn] = m;
        }
    }
    __syncthreads();
#pragma unroll
    for (int mt = 0; mt < 4; mt++)
#pragma unroll
        for (int h = 0; h < 2; h++) {
            int row = mBase + mt * 16 + h * 8 + g;
            float m = fmaxf(fmaxf(redA[row * 4], redA[row * 4 + 1]),
                            fmaxf(redA[row * 4 + 2], redA[row * 4 + 3]));
            rmax[mt][h] = m * INV_TEMP;
        }

    float rinv[4][2];
#pragma unroll
    for (int mt = 0; mt < 4; mt++) {
#pragma unroll
        for (int h = 0; h < 2; h++) {
            float s = 0.0f;
#pragma unroll
            for (int nt = 0; nt < 8; nt++) {
#pragma unroll
                for (int e2 = 0; e2 < 2; e2++) {
                    float w = __expf(acc[mt][nt][h * 2 + e2] * INV_TEMP - rmax[mt][h]);
                    acc[mt][nt][h * 2 + e2] = w;
                    s += w;
                }
            }
            s += __shfl_xor_sync(0xffffffffu, s, 1);
            s += __shfl_xor_sync(0xffffffffu, s, 2);
            if (t == 0) redB[(mBase + mt * 16 + h * 8 + g) * 4 + wn] = s;
        }
    }
    __syncthreads();
#pragma unroll
    for (int mt = 0; mt < 4; mt++)
#pragma unroll
        for (int h = 0; h < 2; h++) {
            int row = mBase + mt * 16 + h * 8 + g;
            float s = redB[row * 4] + redB[row * 4 + 1] + redB[row * 4 + 2] + redB[row * 4 + 3];
            rinv[mt][h] = 1.0f / s;
        }

#pragma unroll
    for (int mt = 0; mt < 4; mt++) {
#pragma unroll
        for (int h = 0; h < 2; h++) {
            int j = j0 + mBase + mt * 16 + h * 8 + g;
#pragma unroll
            for (int nt = 0; nt < 8; nt++) {
                int col = nBase + nt * 8 + 2 * t;
                float w0 = acc[mt][nt][h * 2 + 0] * rinv[mt][h];
                float w1 = acc[mt][nt][h * 2 + 1] * rinv[mt][h];
                __nv_bfloat16 h0, l0, h1, l1;
                split_bf16(w0, h0, l0);
                split_bf16(w1, h1, l1);
                size_t o = (size_t)j * C_ + col;
                *reinterpret_cast<uint32_t*>(Ks_hi + o) = pack2(h0, h1);
                *reinterpret_cast<uint32_t*>(Ks_lo + o) = pack2(l0, l1);
            }
        }
    }
}

// ---------------------------------------------------------------------------
// q softmax over hw (rows of 4096), 512 threads: fp32 -> bf16 hi/lo
// ---------------------------------------------------------------------------
__global__ void __launch_bounds__(512) qsoftmax_kernel(
    const float* __restrict__ Qlog,
    __nv_bfloat16* __restrict__ Qs_hi, __nv_bfloat16* __restrict__ Qs_lo)
{
    constexpr int NT = 512, NE = 8;
    const float* row = Qlog + (size_t)blockIdx.x * HW_;
    __shared__ float sred[32];
    const int tid = threadIdx.x;
    const int lane = tid & 31;
    const int wid = tid >> 5;

    float v[NE];
    float m = -1e30f;
#pragma unroll
    for (int e = 0; e < NE; e++) {
        v[e] = row[tid + e * NT] * INV_TEMP;
        m = fmaxf(m, v[e]);
    }
#pragma unroll
    for (int o = 16; o > 0; o >>= 1) m = fmaxf(m, __shfl_xor_sync(0xffffffffu, m, o));
    if (lane == 0) sred[wid] = m;
    __syncthreads();
    if (wid == 0) {
        float tv = (lane < 16) ? sred[lane] : -1e30f;
#pragma unroll
        for (int o = 16; o > 0; o >>= 1) tv = fmaxf(tv, __shfl_xor_sync(0xffffffffu, tv, o));
        if (lane == 0) sred[0] = tv;
    }
    __syncthreads();
    m = sred[0];
    __syncthreads();

    float sum = 0.0f;
#pragma unroll
    for (int e = 0; e < NE; e++) {
        v[e] = __expf(v[e] - m);
        sum += v[e];
    }
#pragma unroll
    for (int o = 16; o > 0; o >>= 1) sum += __shfl_xor_sync(0xffffffffu, sum, o);
    if (lane == 0) sred[wid] = sum;
    __syncthreads();
    if (wid == 0) {
        float tv = (lane < 16) ? sred[lane] : 0.0f;
#pragma unroll
        for (int o = 16; o > 0; o >>= 1) tv += __shfl_xor_sync(0xffffffffu, tv, o);
        if (lane == 0) sred[0] = tv;
    }
    __syncthreads();
    float inv = 1.0f / sred[0];
    size_t base = (size_t)blockIdx.x * HW_;
#pragma unroll
    for (int e = 0; e < NE; e++) {
        float w = v[e] * inv;
        __nv_bfloat16 h, l;
        split_bf16(w, h, l);
        Qs_hi[base + tid + e * NT] = h;
        Qs_lo[base + tid + e * NT] = l;
    }
}

// Zero T2 + G + out in one launch
__global__ void zero3_kernel(float* __restrict__ a, int na,
                             float* __restrict__ b, int nb,
                             float* __restrict__ c, int nc)
{
    int i = blockIdx.x * blockDim.x + threadIdx.x;
    if (i < na) a[i] = 0.0f;
    else if (i < na + nb) b[i - na] = 0.0f;
    else if (i < na + nb + nc) c[i - na - nb] = 0.0f;
}

__global__ void zero_kernel(float* __restrict__ p, int n)
{
    int i = blockIdx.x * blockDim.x + threadIdx.x;
    if (i < n) p[i] = 0.0f;
}

// ---------------------------------------------------------------------------
// Launch
// ---------------------------------------------------------------------------
extern "C" void kernel_launch(void* const* d_in, const int* in_sizes, int n_in,
                              void* d_out, int out_size)
{
    (void)in_sizes; (void)n_in; (void)out_size;
    const float* query = (const float*)d_in[0]; // (C, HW)
    const float* key   = (const float*)d_in[1]; // (C, S)
    const float* value = (const float*)d_in[2]; // (C, S)
    const float* Wq    = (const float*)d_in[3]; // (C, C)
    const float* Wk    = (const float*)d_in[4];
    const float* Wv    = (const float*)d_in[5];
    float* out = (float*)d_out;                 // (C, HW)

    static bool s_init = false;
    static cudaStream_t s1, s2;
    static cudaEvent_t evF, evJ1, evJ2;
    if (!s_init) {
        cudaStreamCreateWithFlags(&s1, cudaStreamNonBlocking);
        cudaStreamCreateWithFlags(&s2, cudaStreamNonBlocking);
        cudaEventCreateWithFlags(&evF,  cudaEventDisableTiming);
        cudaEventCreateWithFlags(&evJ1, cudaEventDisableTiming);
        cudaEventCreateWithFlags(&evJ2, cudaEventDisableTiming);
        cudaFuncSetAttribute(gemm_uni_kernel<false, true>, cudaFuncAttributeMaxDynamicSharedMemorySize, GEMM_SMEM);
        cudaFuncSetAttribute(gemm_uni_kernel<true, false>, cudaFuncAttributeMaxDynamicSharedMemorySize, GEMM_SMEM);
        cudaFuncSetAttribute(gemm_ksm_kernel, cudaFuncAttributeMaxDynamicSharedMemorySize, KSM_SMEM);
        s_init = true;
    }

    __nv_bfloat16 *Ks_hi, *Ks_lo, *Qs_hi, *Qs_lo;
    __nv_bfloat16 *Wq_hi, *Wq_lo, *Wk_hi, *Wk_lo, *Wv_hi, *Wv_lo;
    float *Qlog, *T2, *G;
    cudaGetSymbolAddress((void**)&Ks_hi, g_Ks_hi);
    cudaGetSymbolAddress((void**)&Ks_lo, g_Ks_lo);
    cudaGetSymbolAddress((void**)&Qs_hi, g_Qs_hi);
    cudaGetSymbolAddress((void**)&Qs_lo, g_Qs_lo);
    cudaGetSymbolAddress((void**)&Wq_hi, g_Wq_hi);
    cudaGetSymbolAddress((void**)&Wq_lo, g_Wq_lo);
    cudaGetSymbolAddress((void**)&Wk_hi, g_Wk_hi);
    cudaGetSymbolAddress((void**)&Wk_lo, g_Wk_lo);
    cudaGetSymbolAddress((void**)&Wv_hi, g_Wv_hi);
    cudaGetSymbolAddress((void**)&Wv_lo, g_Wv_lo);
    cudaGetSymbolAddress((void**)&Qlog,  g_Qlog);
    cudaGetSymbolAddress((void**)&T2,    g_T2);
    cudaGetSymbolAddress((void**)&G,     g_G);

    // main: weight conversion, then fork
    convW3_kernel<<<dim3(64, 1, 3), 256>>>(Wq, Wk, Wv, Wq_hi, Wq_lo, Wk_hi, Wk_lo, Wv_hi, Wv_lo);
    cudaEventRecord(evF, 0);
    cudaStreamWaitEvent(s1, evF, 0);
    cudaStreamWaitEvent(s2, evF, 0);

    // s1: Ks path (GEMM1 + fused k-softmax)
    gemm_ksm_kernel<<<SA_ / 128, 256, KSM_SMEM, s1>>>(key + S0_, Wk_hi, Wk_lo, Ks_hi, Ks_lo);
    cudaEventRecord(evJ1, s1);

    // s2: Qs path (split-K 4 -> 256 CTAs)
    zero_kernel<<<(C_ * HW_ + 255) / 256, 256, 0, s2>>>(Qlog, C_ * HW_);
    gemm_uni_kernel<false, true><<<dim3(HW_ / 128, C_ / 128, 4), 256, GEMM_SMEM, s2>>>(
        Wq_hi, Wq_lo, nullptr, C_, nullptr, nullptr, query, HW_, Qlog, HW_, C_ / 4);
    qsoftmax_kernel<<<C_, 512, 0, s2>>>(Qlog, Qs_hi, Qs_lo);
    cudaEventRecord(evJ2, s2);

    // main: zero T2 + G + out in one launch (overlaps both branches)
    {
        int total = C_ * C_ * 2 + C_ * HW_;
        zero3_kernel<<<(total + 255) / 256, 256>>>(T2, C_ * C_, G, C_ * C_, out, C_ * HW_);
    }

    // join Ks path -> GEMM3 (T2, split-K 64), GEMM4 (G, split-K 8)
    cudaStreamWaitEvent(0, evJ1, 0);
    gemm_uni_kernel<true, false><<<dim3(C_ / 128, C_ / 128, 64), 256, GEMM_SMEM>>>(
        nullptr, nullptr, value + S0_, S_, Ks_hi, Ks_lo, nullptr, C_, T2, C_, SA_ / 64);
    gemm_uni_kernel<false, true><<<dim3(C_ / 128, C_ / 128, 8), 256, GEMM_SMEM>>>(
        Wv_hi, Wv_lo, nullptr, C_, nullptr, nullptr, T2, C_, G, C_, C_ / 8);

    // join Qs path -> GEMM5 (split-K 4)
    cudaStreamWaitEvent(0, evJ2, 0);
    gemm_uni_kernel<true, false><<<dim3(HW_ / 128, C_ / 128, 4), 256, GEMM_SMEM>>>(
        nullptr, nullptr, G, C_, Qs_hi, Qs_lo, nullptr, HW_, out, HW_, C_ / 4);
}